// round 2
// baseline (speedup 1.0000x reference)
#include <cuda_runtime.h>
#include <cuda_bf16.h>
#include <math.h>

#define N_NODES 100000
#define IN_CH   128
#define HIDDEN  128
#define OUT_CH  64
#define N_POS   600000
#define N_EDGES_TOT 1200000

// ---------------- scratch (no cudaMalloc allowed) ----------------
__device__ float g_h1[(size_t)N_NODES * HIDDEN];   // x @ W1
__device__ float g_z1[(size_t)N_NODES * HIDDEN];   // relu(agg1 + b1)
__device__ float g_h2[(size_t)N_NODES * OUT_CH];   // z1 @ W2
__device__ float g_z2[(size_t)N_NODES * OUT_CH];   // agg2 + b2
__device__ float g_dinv[N_NODES];
__device__ int   g_cnt[N_NODES];
__device__ int   g_cur[N_NODES];
__device__ int   g_offs[N_NODES + 1];
__device__ int   g_esrc[N_POS];

// ---------------- CSR build ----------------
__global__ void k_zero() {
    int i = blockIdx.x * blockDim.x + threadIdx.x;
    if (i < N_NODES) { g_cnt[i] = 0; g_cur[i] = 0; }
}

__global__ void k_hist(const int* __restrict__ pos_ei) {
    int e = blockIdx.x * blockDim.x + threadIdx.x;
    if (e < N_POS) {
        int d = pos_ei[N_POS + e];   // row 1 = dst
        atomicAdd(&g_cnt[d], 1);
    }
}

__global__ void k_dinv() {
    int i = blockIdx.x * blockDim.x + threadIdx.x;
    if (i < N_NODES) g_dinv[i] = rsqrtf((float)g_cnt[i] + 1.0f);
}

// single-block exclusive scan over g_cnt -> g_offs
__global__ void k_scan() {
    __shared__ int buf[1024];
    __shared__ int carry;
    if (threadIdx.x == 0) carry = 0;
    __syncthreads();
    for (int base = 0; base < N_NODES; base += 1024) {
        int i = base + threadIdx.x;
        int v = (i < N_NODES) ? g_cnt[i] : 0;
        buf[threadIdx.x] = v;
        __syncthreads();
        #pragma unroll
        for (int off = 1; off < 1024; off <<= 1) {
            int t = (threadIdx.x >= off) ? buf[threadIdx.x - off] : 0;
            __syncthreads();
            buf[threadIdx.x] += t;
            __syncthreads();
        }
        if (i < N_NODES) g_offs[i] = carry + buf[threadIdx.x] - v;  // exclusive
        __syncthreads();
        if (threadIdx.x == 0) carry += buf[1023];
        __syncthreads();
    }
    if (threadIdx.x == 0) g_offs[N_NODES] = carry;
}

__global__ void k_fill(const int* __restrict__ pos_ei) {
    int e = blockIdx.x * blockDim.x + threadIdx.x;
    if (e < N_POS) {
        int s = pos_ei[e];
        int d = pos_ei[N_POS + e];
        int p = g_offs[d] + atomicAdd(&g_cur[d], 1);
        g_esrc[p] = s;
    }
}

// ---------------- GEMM body: C[n][OUTC] = A[n][128] @ W[128][OUTC] ----------------
// 256 threads; thread computes 4 rows x 4 cols. W k-slice + transposed x tile in smem.
template <int OUTC>
__device__ __forceinline__ void gemm_body(const float* __restrict__ A,
                                          const float* __restrict__ W,
                                          float* __restrict__ C, int nrows) {
    constexpr int CG = OUTC / 4;      // col groups (float4 per thread)
    constexpr int RG = 256 / CG;      // row groups
    constexpr int BR = RG * 4;        // rows per block
    __shared__ float Wc[32 * OUTC];         // k-slice of W
    __shared__ float xs[32][BR + 4];        // [k][row]

    int tid = threadIdx.x;
    int cg = tid % CG;
    int rg = tid / CG;
    int row0 = blockIdx.x * BR;

    float acc[4][4];
    #pragma unroll
    for (int r = 0; r < 4; r++)
        #pragma unroll
        for (int c = 0; c < 4; c++) acc[r][c] = 0.0f;

    for (int kb = 0; kb < 128; kb += 32) {
        __syncthreads();
        const float4* Wg = (const float4*)(W + (size_t)kb * OUTC);
        #pragma unroll
        for (int i = tid; i < 32 * OUTC / 4; i += 256)
            ((float4*)Wc)[i] = Wg[i];
        for (int i = tid; i < BR * 8; i += 256) {
            int r = i / 8, q = i % 8;
            int grow = row0 + r;
            float4 v = make_float4(0.f, 0.f, 0.f, 0.f);
            if (grow < nrows)
                v = ((const float4*)(A + (size_t)grow * 128 + kb))[q];
            xs[4 * q + 0][r] = v.x;
            xs[4 * q + 1][r] = v.y;
            xs[4 * q + 2][r] = v.z;
            xs[4 * q + 3][r] = v.w;
        }
        __syncthreads();
        #pragma unroll
        for (int kk = 0; kk < 32; kk++) {
            float4 w = *(const float4*)(&Wc[kk * OUTC + cg * 4]);
            #pragma unroll
            for (int r = 0; r < 4; r++) {
                float xv = xs[kk][rg * 4 + r];
                acc[r][0] += xv * w.x;
                acc[r][1] += xv * w.y;
                acc[r][2] += xv * w.z;
                acc[r][3] += xv * w.w;
            }
        }
    }
    #pragma unroll
    for (int r = 0; r < 4; r++) {
        int grow = row0 + rg * 4 + r;
        if (grow < nrows) {
            float4 o = make_float4(acc[r][0], acc[r][1], acc[r][2], acc[r][3]);
            *(float4*)(&C[(size_t)grow * OUTC + cg * 4]) = o;
        }
    }
}

__global__ __launch_bounds__(256) void k_gemm1(const float* __restrict__ x,
                                               const float* __restrict__ W1) {
    gemm_body<128>(x, W1, g_h1, N_NODES);
}

__global__ __launch_bounds__(256) void k_gemm2(const float* __restrict__ W2) {
    gemm_body<64>(g_z1, W2, g_h2, N_NODES);
}

// ---------------- layer-1 aggregation: warp per dst node, 128 feats ----------------
__global__ void k_agg1(const float* __restrict__ b1) {
    int gw = (blockIdx.x * blockDim.x + threadIdx.x) >> 5;
    int lane = threadIdx.x & 31;
    if (gw >= N_NODES) return;
    int d = gw;
    float dv = g_dinv[d];
    float self = dv * dv;

    float4 h = ((const float4*)(g_h1 + (size_t)d * 128))[lane];
    float4 acc = make_float4(h.x * self, h.y * self, h.z * self, h.w * self);

    int e0 = g_offs[d], e1 = g_offs[d + 1];
    for (int j = e0; j < e1; j++) {
        int s = g_esrc[j];
        float nrm = dv * g_dinv[s];
        float4 v = ((const float4*)(g_h1 + (size_t)s * 128))[lane];
        acc.x += v.x * nrm; acc.y += v.y * nrm;
        acc.z += v.z * nrm; acc.w += v.w * nrm;
    }
    float4 bb = ((const float4*)b1)[lane];
    acc.x = fmaxf(acc.x + bb.x, 0.0f);
    acc.y = fmaxf(acc.y + bb.y, 0.0f);
    acc.z = fmaxf(acc.z + bb.z, 0.0f);
    acc.w = fmaxf(acc.w + bb.w, 0.0f);
    ((float4*)(g_z1 + (size_t)d * 128))[lane] = acc;
}

// ---------------- layer-2 aggregation: warp per dst node, 64 feats ----------------
__global__ void k_agg2(const float* __restrict__ b2) {
    int gw = (blockIdx.x * blockDim.x + threadIdx.x) >> 5;
    int lane = threadIdx.x & 31;
    if (gw >= N_NODES) return;
    int d = gw;
    float dv = g_dinv[d];
    float self = dv * dv;

    float2 h = ((const float2*)(g_h2 + (size_t)d * 64))[lane];
    float2 acc = make_float2(h.x * self, h.y * self);

    int e0 = g_offs[d], e1 = g_offs[d + 1];
    for (int j = e0; j < e1; j++) {
        int s = g_esrc[j];
        float nrm = dv * g_dinv[s];
        float2 v = ((const float2*)(g_h2 + (size_t)s * 64))[lane];
        acc.x += v.x * nrm; acc.y += v.y * nrm;
    }
    float2 bb = ((const float2*)b2)[lane];
    acc.x += bb.x; acc.y += bb.y;
    ((float2*)(g_z2 + (size_t)d * 64))[lane] = acc;
}

// ---------------- decode: warp per edge, dot over 64 feats ----------------
__global__ void k_decode(const int* __restrict__ pos_ei,
                         const int* __restrict__ neg_ei,
                         float* __restrict__ out) {
    int e = (blockIdx.x * blockDim.x + threadIdx.x) >> 5;
    int lane = threadIdx.x & 31;
    if (e >= N_EDGES_TOT) return;
    int a, b;
    if (e < N_POS) { a = pos_ei[e]; b = pos_ei[N_POS + e]; }
    else { int f = e - N_POS; a = neg_ei[f]; b = neg_ei[N_POS + f]; }

    float2 u = ((const float2*)(g_z2 + (size_t)a * 64))[lane];
    float2 v = ((const float2*)(g_z2 + (size_t)b * 64))[lane];
    float s = u.x * v.x + u.y * v.y;
    #pragma unroll
    for (int o = 16; o > 0; o >>= 1) s += __shfl_xor_sync(0xffffffffu, s, o);
    if (lane == 0) out[e] = s;
}

// ---------------- launch ----------------
extern "C" void kernel_launch(void* const* d_in, const int* in_sizes, int n_in,
                              void* d_out, int out_size) {
    const float* x   = (const float*)d_in[0];
    const int*   pos = (const int*)d_in[1];
    const int*   neg = (const int*)d_in[2];
    const float* W1  = (const float*)d_in[3];
    const float* b1  = (const float*)d_in[4];
    const float* W2  = (const float*)d_in[5];
    const float* b2  = (const float*)d_in[6];
    float* out = (float*)d_out;

    const int T = 256;
    k_zero<<<(N_NODES + T - 1) / T, T>>>();
    k_hist<<<(N_POS + T - 1) / T, T>>>(pos);
    k_dinv<<<(N_NODES + T - 1) / T, T>>>();
    k_scan<<<1, 1024>>>();
    k_fill<<<(N_POS + T - 1) / T, T>>>(pos);

    // GEMM1: h1 = x @ W1  (BR=32 rows/block)
    k_gemm1<<<(N_NODES + 31) / 32, 256>>>(x, W1);
    // agg1 + bias + relu -> z1
    k_agg1<<<(N_NODES * 32 + T - 1) / T, T>>>(b1);
    // GEMM2: h2 = z1 @ W2 (BR=64 rows/block)
    k_gemm2<<<(N_NODES + 63) / 64, 256>>>(W2);
    // agg2 + bias -> z2
    k_agg2<<<(N_NODES * 32 + T - 1) / T, T>>>(b2);
    // decode
    k_decode<<<((size_t)N_EDGES_TOT * 32 + T - 1) / T, T>>>(pos, neg, out);
}

// round 3
// speedup vs baseline: 1.3413x; 1.3413x over previous
#include <cuda_runtime.h>
#include <cuda_bf16.h>
#include <math.h>

#define N_NODES 100000
#define IN_CH   128
#define HIDDEN  128
#define OUT_CH  64
#define N_POS   600000
#define N_EDGES_TOT 1200000

#define SCAN_B 512
#define NB ((N_NODES + SCAN_B - 1) / SCAN_B)   // 196

// ---------------- scratch (no cudaMalloc allowed) ----------------
__device__ float g_h1[(size_t)N_NODES * HIDDEN];   // x @ W1
__device__ float g_z1[(size_t)N_NODES * HIDDEN];   // relu(agg1 + b1)
__device__ float g_h2[(size_t)N_NODES * OUT_CH];   // z1 @ W2
__device__ float g_z2[(size_t)N_NODES * OUT_CH];   // agg2 + b2
__device__ float g_dinv[N_NODES];
__device__ int   g_cnt[N_NODES];
__device__ int   g_cur[N_NODES];
__device__ int   g_offs[N_NODES + 1];
__device__ int   g_esrc[N_POS];
__device__ int   g_bsum[NB];

// ---------------- CSR build ----------------
__global__ void k_zero() {
    int i = blockIdx.x * blockDim.x + threadIdx.x;
    if (i < N_NODES) { g_cnt[i] = 0; g_cur[i] = 0; }
}

__global__ void k_hist(const int* __restrict__ pos_ei) {
    int e = blockIdx.x * blockDim.x + threadIdx.x;
    if (e < N_POS) {
        int d = pos_ei[N_POS + e];   // row 1 = dst
        atomicAdd(&g_cnt[d], 1);
    }
}

// Phase A: per-block exclusive scan (512 elems/block) + dinv + block sums
__global__ __launch_bounds__(SCAN_B) void k_scanA() {
    __shared__ int wsum[16];
    int i = blockIdx.x * SCAN_B + threadIdx.x;
    int lane = threadIdx.x & 31, wid = threadIdx.x >> 5;
    int v = (i < N_NODES) ? g_cnt[i] : 0;
    if (i < N_NODES) g_dinv[i] = rsqrtf((float)v + 1.0f);

    int s = v;
    #pragma unroll
    for (int o = 1; o < 32; o <<= 1) {
        int t = __shfl_up_sync(0xffffffffu, s, o);
        if (lane >= o) s += t;
    }
    if (lane == 31) wsum[wid] = s;
    __syncthreads();
    if (wid == 0) {
        int w = (lane < 16) ? wsum[lane] : 0;
        #pragma unroll
        for (int o = 1; o < 16; o <<= 1) {
            int t = __shfl_up_sync(0xffffffffu, w, o);
            if (lane >= o) w += t;
        }
        if (lane < 16) wsum[lane] = w;
    }
    __syncthreads();
    int excl = s - v + (wid > 0 ? wsum[wid - 1] : 0);
    if (i < N_NODES) g_offs[i] = excl;           // block-local exclusive
    if (threadIdx.x == 0) g_bsum[blockIdx.x] = wsum[15];  // block total
}

// Phase B: single-block exclusive scan of NB block sums (NB <= 256)
__global__ __launch_bounds__(256) void k_scanB() {
    __shared__ int wsum[8];
    int lane = threadIdx.x & 31, wid = threadIdx.x >> 5;
    int v = (threadIdx.x < NB) ? g_bsum[threadIdx.x] : 0;
    int s = v;
    #pragma unroll
    for (int o = 1; o < 32; o <<= 1) {
        int t = __shfl_up_sync(0xffffffffu, s, o);
        if (lane >= o) s += t;
    }
    if (lane == 31) wsum[wid] = s;
    __syncthreads();
    if (wid == 0) {
        int w = (lane < 8) ? wsum[lane] : 0;
        #pragma unroll
        for (int o = 1; o < 8; o <<= 1) {
            int t = __shfl_up_sync(0xffffffffu, w, o);
            if (lane >= o) w += t;
        }
        if (lane < 8) wsum[lane] = w;
    }
    __syncthreads();
    int excl = s - v + (wid > 0 ? wsum[wid - 1] : 0);
    if (threadIdx.x < NB) g_bsum[threadIdx.x] = excl;
    if (threadIdx.x == NB - 1) g_offs[N_NODES] = excl + v;  // grand total
}

// Phase C: add block offsets
__global__ __launch_bounds__(SCAN_B) void k_scanC() {
    int i = blockIdx.x * SCAN_B + threadIdx.x;
    if (i < N_NODES) g_offs[i] += g_bsum[blockIdx.x];
}

__global__ void k_fill(const int* __restrict__ pos_ei) {
    int e = blockIdx.x * blockDim.x + threadIdx.x;
    if (e < N_POS) {
        int s = pos_ei[e];
        int d = pos_ei[N_POS + e];
        int p = g_offs[d] + atomicAdd(&g_cur[d], 1);
        g_esrc[p] = s;
    }
}

// ---------------- GEMM body: C[n][OUTC] = A[n][128] @ W[128][OUTC] ----------------
template <int OUTC>
__device__ __forceinline__ void gemm_body(const float* __restrict__ A,
                                          const float* __restrict__ W,
                                          float* __restrict__ C, int nrows) {
    constexpr int CG = OUTC / 4;      // col groups (float4 per thread)
    constexpr int RG = 256 / CG;      // row groups
    constexpr int BR = RG * 4;        // rows per block
    __shared__ float Wc[32 * OUTC];         // k-slice of W
    __shared__ float xs[32][BR + 4];        // [k][row]

    int tid = threadIdx.x;
    int cg = tid % CG;
    int rg = tid / CG;
    int row0 = blockIdx.x * BR;

    float acc[4][4];
    #pragma unroll
    for (int r = 0; r < 4; r++)
        #pragma unroll
        for (int c = 0; c < 4; c++) acc[r][c] = 0.0f;

    for (int kb = 0; kb < 128; kb += 32) {
        __syncthreads();
        const float4* Wg = (const float4*)(W + (size_t)kb * OUTC);
        #pragma unroll
        for (int i = tid; i < 32 * OUTC / 4; i += 256)
            ((float4*)Wc)[i] = Wg[i];
        for (int i = tid; i < BR * 8; i += 256) {
            int r = i / 8, q = i % 8;
            int grow = row0 + r;
            float4 v = make_float4(0.f, 0.f, 0.f, 0.f);
            if (grow < nrows)
                v = ((const float4*)(A + (size_t)grow * 128 + kb))[q];
            xs[4 * q + 0][r] = v.x;
            xs[4 * q + 1][r] = v.y;
            xs[4 * q + 2][r] = v.z;
            xs[4 * q + 3][r] = v.w;
        }
        __syncthreads();
        #pragma unroll
        for (int kk = 0; kk < 32; kk++) {
            float4 w = *(const float4*)(&Wc[kk * OUTC + cg * 4]);
            #pragma unroll
            for (int r = 0; r < 4; r++) {
                float xv = xs[kk][rg * 4 + r];
                acc[r][0] += xv * w.x;
                acc[r][1] += xv * w.y;
                acc[r][2] += xv * w.z;
                acc[r][3] += xv * w.w;
            }
        }
    }
    #pragma unroll
    for (int r = 0; r < 4; r++) {
        int grow = row0 + rg * 4 + r;
        if (grow < nrows) {
            float4 o = make_float4(acc[r][0], acc[r][1], acc[r][2], acc[r][3]);
            *(float4*)(&C[(size_t)grow * OUTC + cg * 4]) = o;
        }
    }
}

__global__ __launch_bounds__(256) void k_gemm1(const float* __restrict__ x,
                                               const float* __restrict__ W1) {
    gemm_body<128>(x, W1, g_h1, N_NODES);
}

__global__ __launch_bounds__(256) void k_gemm2(const float* __restrict__ W2) {
    gemm_body<64>(g_z1, W2, g_h2, N_NODES);
}

// ---------------- layer-1 aggregation: warp per dst node, 128 feats ----------------
__global__ void k_agg1(const float* __restrict__ b1) {
    int gw = (blockIdx.x * blockDim.x + threadIdx.x) >> 5;
    int lane = threadIdx.x & 31;
    if (gw >= N_NODES) return;
    int d = gw;
    float dv = g_dinv[d];
    float self = dv * dv;

    float4 h = ((const float4*)(g_h1 + (size_t)d * 128))[lane];
    float4 acc = make_float4(h.x * self, h.y * self, h.z * self, h.w * self);

    int e0 = g_offs[d], e1 = g_offs[d + 1];
    for (int j = e0; j < e1; j++) {
        int s = g_esrc[j];
        float nrm = dv * g_dinv[s];
        float4 v = ((const float4*)(g_h1 + (size_t)s * 128))[lane];
        acc.x += v.x * nrm; acc.y += v.y * nrm;
        acc.z += v.z * nrm; acc.w += v.w * nrm;
    }
    float4 bb = ((const float4*)b1)[lane];
    acc.x = fmaxf(acc.x + bb.x, 0.0f);
    acc.y = fmaxf(acc.y + bb.y, 0.0f);
    acc.z = fmaxf(acc.z + bb.z, 0.0f);
    acc.w = fmaxf(acc.w + bb.w, 0.0f);
    ((float4*)(g_z1 + (size_t)d * 128))[lane] = acc;
}

// ---------------- layer-2 aggregation: warp per dst node, 64 feats ----------------
__global__ void k_agg2(const float* __restrict__ b2) {
    int gw = (blockIdx.x * blockDim.x + threadIdx.x) >> 5;
    int lane = threadIdx.x & 31;
    if (gw >= N_NODES) return;
    int d = gw;
    float dv = g_dinv[d];
    float self = dv * dv;

    float2 h = ((const float2*)(g_h2 + (size_t)d * 64))[lane];
    float2 acc = make_float2(h.x * self, h.y * self);

    int e0 = g_offs[d], e1 = g_offs[d + 1];
    for (int j = e0; j < e1; j++) {
        int s = g_esrc[j];
        float nrm = dv * g_dinv[s];
        float2 v = ((const float2*)(g_h2 + (size_t)s * 64))[lane];
        acc.x += v.x * nrm; acc.y += v.y * nrm;
    }
    float2 bb = ((const float2*)b2)[lane];
    acc.x += bb.x; acc.y += bb.y;
    ((float2*)(g_z2 + (size_t)d * 64))[lane] = acc;
}

// ---------------- decode: warp per edge, dot over 64 feats ----------------
__global__ void k_decode(const int* __restrict__ pos_ei,
                         const int* __restrict__ neg_ei,
                         float* __restrict__ out) {
    int e = (blockIdx.x * blockDim.x + threadIdx.x) >> 5;
    int lane = threadIdx.x & 31;
    if (e >= N_EDGES_TOT) return;
    int a, b;
    if (e < N_POS) { a = pos_ei[e]; b = pos_ei[N_POS + e]; }
    else { int f = e - N_POS; a = neg_ei[f]; b = neg_ei[N_POS + f]; }

    float2 u = ((const float2*)(g_z2 + (size_t)a * 64))[lane];
    float2 v = ((const float2*)(g_z2 + (size_t)b * 64))[lane];
    float s = u.x * v.x + u.y * v.y;
    #pragma unroll
    for (int o = 16; o > 0; o >>= 1) s += __shfl_xor_sync(0xffffffffu, s, o);
    if (lane == 0) out[e] = s;
}

// ---------------- launch ----------------
extern "C" void kernel_launch(void* const* d_in, const int* in_sizes, int n_in,
                              void* d_out, int out_size) {
    const float* x   = (const float*)d_in[0];
    const int*   pos = (const int*)d_in[1];
    const int*   neg = (const int*)d_in[2];
    const float* W1  = (const float*)d_in[3];
    const float* b1  = (const float*)d_in[4];
    const float* W2  = (const float*)d_in[5];
    const float* b2  = (const float*)d_in[6];
    float* out = (float*)d_out;

    const int T = 256;
    k_zero<<<(N_NODES + T - 1) / T, T>>>();
    k_hist<<<(N_POS + T - 1) / T, T>>>(pos);
    k_scanA<<<NB, SCAN_B>>>();
    k_scanB<<<1, 256>>>();
    k_scanC<<<NB, SCAN_B>>>();
    k_fill<<<(N_POS + T - 1) / T, T>>>(pos);

    // GEMM1: h1 = x @ W1  (BR=32 rows/block)
    k_gemm1<<<(N_NODES + 31) / 32, 256>>>(x, W1);
    // agg1 + bias + relu -> z1
    k_agg1<<<(N_NODES * 32 + T - 1) / T, T>>>(b1);
    // GEMM2: h2 = z1 @ W2 (BR=64 rows/block)
    k_gemm2<<<(N_NODES + 63) / 64, 256>>>(W2);
    // agg2 + bias -> z2
    k_agg2<<<(N_NODES * 32 + T - 1) / T, T>>>(b2);
    // decode
    k_decode<<<((size_t)N_EDGES_TOT * 32 + T - 1) / T, T>>>(pos, neg, out);
}

// round 7
// speedup vs baseline: 1.3690x; 1.0207x over previous
#include <cuda_runtime.h>
#include <cuda_bf16.h>
#include <mma.h>
#include <math.h>
#include <stdint.h>

using namespace nvcuda;

#define N_NODES 100000
#define IN_CH   128
#define HIDDEN  128
#define OUT_CH  64
#define N_POS   600000
#define N_EDGES_TOT 1200000

#define SCAN_B 512
#define NB ((N_NODES + SCAN_B - 1) / SCAN_B)   // 196

// ---------------- scratch (no cudaMalloc allowed) ----------------
__device__ float g_h1[(size_t)N_NODES * HIDDEN];   // x @ W1
__device__ float g_z1[(size_t)N_NODES * HIDDEN];   // relu(agg1 + b1)
__device__ float g_h2[(size_t)N_NODES * OUT_CH];   // z1 @ W2
__device__ float g_z2[(size_t)N_NODES * OUT_CH];   // agg2 + b2
__device__ float g_dinv[N_NODES];
__device__ int   g_cnt[N_NODES];
__device__ int   g_cur[N_NODES];
__device__ int   g_offs[N_NODES + 1];
__device__ int   g_esrc[N_POS];
__device__ int   g_bsum[NB];

// ---------------- helpers ----------------
// pack two fp32 into bf16x2: elem a -> low half, elem b -> high half
__device__ __forceinline__ uint32_t pack2(float a, float b) {
    uint32_t r;
    asm("cvt.rn.satfinite.bf16x2.f32 %0, %1, %2;" : "=r"(r) : "f"(b), "f"(a));
    return r;
}
__device__ __forceinline__ float bf16_round(float v) {
    return __bfloat162float(__float2bfloat16(v));
}

// ---------------- CSR build ----------------
__global__ void k_zero() {
    int i = blockIdx.x * blockDim.x + threadIdx.x;
    if (i < N_NODES) { g_cnt[i] = 0; g_cur[i] = 0; }
}

__global__ void k_hist(const int* __restrict__ pos_ei) {
    int e = blockIdx.x * blockDim.x + threadIdx.x;
    if (e < N_POS) {
        int d = pos_ei[N_POS + e];   // row 1 = dst
        atomicAdd(&g_cnt[d], 1);
    }
}

__global__ __launch_bounds__(SCAN_B) void k_scanA() {
    __shared__ int wsum[16];
    int i = blockIdx.x * SCAN_B + threadIdx.x;
    int lane = threadIdx.x & 31, wid = threadIdx.x >> 5;
    int v = (i < N_NODES) ? g_cnt[i] : 0;
    if (i < N_NODES) g_dinv[i] = rsqrtf((float)v + 1.0f);

    int s = v;
    #pragma unroll
    for (int o = 1; o < 32; o <<= 1) {
        int t = __shfl_up_sync(0xffffffffu, s, o);
        if (lane >= o) s += t;
    }
    if (lane == 31) wsum[wid] = s;
    __syncthreads();
    if (wid == 0) {
        int w = (lane < 16) ? wsum[lane] : 0;
        #pragma unroll
        for (int o = 1; o < 16; o <<= 1) {
            int t = __shfl_up_sync(0xffffffffu, w, o);
            if (lane >= o) w += t;
        }
        if (lane < 16) wsum[lane] = w;
    }
    __syncthreads();
    int excl = s - v + (wid > 0 ? wsum[wid - 1] : 0);
    if (i < N_NODES) g_offs[i] = excl;
    if (threadIdx.x == 0) g_bsum[blockIdx.x] = wsum[15];
}

__global__ __launch_bounds__(256) void k_scanB() {
    __shared__ int wsum[8];
    int lane = threadIdx.x & 31, wid = threadIdx.x >> 5;
    int v = (threadIdx.x < NB) ? g_bsum[threadIdx.x] : 0;
    int s = v;
    #pragma unroll
    for (int o = 1; o < 32; o <<= 1) {
        int t = __shfl_up_sync(0xffffffffu, s, o);
        if (lane >= o) s += t;
    }
    if (lane == 31) wsum[wid] = s;
    __syncthreads();
    if (wid == 0) {
        int w = (lane < 8) ? wsum[lane] : 0;
        #pragma unroll
        for (int o = 1; o < 8; o <<= 1) {
            int t = __shfl_up_sync(0xffffffffu, w, o);
            if (lane >= o) w += t;
        }
        if (lane < 8) wsum[lane] = w;
    }
    __syncthreads();
    int excl = s - v + (wid > 0 ? wsum[wid - 1] : 0);
    if (threadIdx.x < NB) g_bsum[threadIdx.x] = excl;
    if (threadIdx.x == NB - 1) g_offs[N_NODES] = excl + v;
}

__global__ __launch_bounds__(SCAN_B) void k_scanC() {
    int i = blockIdx.x * SCAN_B + threadIdx.x;
    if (i < N_NODES) g_offs[i] += g_bsum[blockIdx.x];
}

__global__ void k_fill(const int* __restrict__ pos_ei) {
    int e = blockIdx.x * blockDim.x + threadIdx.x;
    if (e < N_POS) {
        int s = pos_ei[e];
        int d = pos_ei[N_POS + e];
        int p = g_offs[d] + atomicAdd(&g_cur[d], 1);
        g_esrc[p] = s;
    }
}

// =================================================================
// WMMA GEMM body: C[nrows][OUTC] = A[nrows][128] @ W[128][OUTC]
// bf16 hi/lo 3-pass split (hi*hi + hi*lo + lo*hi), fp32 accumulate.
// 256 threads = 8 warps x 16 rows = 128 rows/CTA. K staged in 32-chunks.
// NOTE: C/A device-global pointers are taken INSIDE device code by the
// wrapper kernels below (host-side __device__ symbol args are invalid).
// =================================================================
#define SA 48   // A smem stride (elems): 96B, 32B-aligned rows

template <int OUTC>
__device__ __forceinline__ void wmma_body(const float* __restrict__ A,
                                          const float* __restrict__ W,
                                          float* __restrict__ C, int nrows) {
    constexpr int SW = OUTC + 16;      // W smem stride (elems)
    __shared__ alignas(256) __nv_bfloat16 sAh[128 * SA];
    __shared__ alignas(256) __nv_bfloat16 sAl[128 * SA];
    __shared__ alignas(256) __nv_bfloat16 sWh[32 * SW];
    __shared__ alignas(256) __nv_bfloat16 sWl[32 * SW];

    const int tid  = threadIdx.x;
    const int warp = tid >> 5;
    const int row0 = blockIdx.x * 128;

    constexpr int NT = OUTC / 16;
    wmma::fragment<wmma::accumulator, 16, 16, 16, float> acc[NT];
    #pragma unroll
    for (int nt = 0; nt < NT; nt++) wmma::fill_fragment(acc[nt], 0.0f);

    for (int kb = 0; kb < 128; kb += 32) {
        // ---- stage A chunk [128 x 32] as bf16 hi/lo ----
        for (int idx = tid * 4; idx < 128 * 32; idx += 1024) {
            int r = idx >> 5, c = idx & 31;
            int grow = row0 + r;
            float4 v = make_float4(0.f, 0.f, 0.f, 0.f);
            if (grow < nrows) v = *(const float4*)(A + (size_t)grow * 128 + kb + c);
            uint32_t h0 = pack2(v.x, v.y), h1 = pack2(v.z, v.w);
            uint32_t l0 = pack2(v.x - bf16_round(v.x), v.y - bf16_round(v.y));
            uint32_t l1 = pack2(v.z - bf16_round(v.z), v.w - bf16_round(v.w));
            *(uint2*)(sAh + r * SA + c) = make_uint2(h0, h1);
            *(uint2*)(sAl + r * SA + c) = make_uint2(l0, l1);
        }
        // ---- stage W chunk [32 x OUTC] as bf16 hi/lo ----
        for (int idx = tid * 4; idx < 32 * OUTC; idx += 1024) {
            int kr = idx / OUTC, n = idx % OUTC;
            float4 v = *(const float4*)(W + (size_t)(kb + kr) * OUTC + n);
            uint32_t h0 = pack2(v.x, v.y), h1 = pack2(v.z, v.w);
            uint32_t l0 = pack2(v.x - bf16_round(v.x), v.y - bf16_round(v.y));
            uint32_t l1 = pack2(v.z - bf16_round(v.z), v.w - bf16_round(v.w));
            *(uint2*)(sWh + kr * SW + n) = make_uint2(h0, h1);
            *(uint2*)(sWl + kr * SW + n) = make_uint2(l0, l1);
        }
        __syncthreads();

        #pragma unroll
        for (int kk = 0; kk < 32; kk += 16) {
            wmma::fragment<wmma::matrix_a, 16, 16, 16, __nv_bfloat16, wmma::row_major> fah, fal;
            wmma::load_matrix_sync(fah, sAh + warp * 16 * SA + kk, SA);
            wmma::load_matrix_sync(fal, sAl + warp * 16 * SA + kk, SA);
            #pragma unroll
            for (int nt = 0; nt < NT; nt++) {
                wmma::fragment<wmma::matrix_b, 16, 16, 16, __nv_bfloat16, wmma::row_major> fbh, fbl;
                wmma::load_matrix_sync(fbh, sWh + kk * SW + nt * 16, SW);
                wmma::load_matrix_sync(fbl, sWl + kk * SW + nt * 16, SW);
                wmma::mma_sync(acc[nt], fah, fbh, acc[nt]);
                wmma::mma_sync(acc[nt], fah, fbl, acc[nt]);
                wmma::mma_sync(acc[nt], fal, fbh, acc[nt]);
            }
        }
        __syncthreads();
    }

    // ---- epilogue: warp tile rows [wr, wr+16) fully in or out (16 | nrows) ----
    int wr = row0 + warp * 16;
    if (wr + 16 <= nrows) {
        #pragma unroll
        for (int nt = 0; nt < NT; nt++)
            wmma::store_matrix_sync(C + (size_t)wr * OUTC + nt * 16, acc[nt],
                                    OUTC, wmma::mem_row_major);
    }
}

// wrapper kernels: device-side references to the __device__ globals
__global__ __launch_bounds__(256) void k_wmma1(const float* __restrict__ x,
                                               const float* __restrict__ W1) {
    wmma_body<128>(x, W1, g_h1, N_NODES);
}
__global__ __launch_bounds__(256) void k_wmma2(const float* __restrict__ W2) {
    wmma_body<64>(g_z1, W2, g_h2, N_NODES);
}

// ---------------- layer-1 aggregation: warp per dst node, 128 feats ----------------
__global__ void k_agg1(const float* __restrict__ b1) {
    int gw = (blockIdx.x * blockDim.x + threadIdx.x) >> 5;
    int lane = threadIdx.x & 31;
    if (gw >= N_NODES) return;
    int d = gw;
    float dv = g_dinv[d];
    float self = dv * dv;

    float4 h = ((const float4*)(g_h1 + (size_t)d * 128))[lane];
    float4 acc = make_float4(h.x * self, h.y * self, h.z * self, h.w * self);

    int e0 = g_offs[d], e1 = g_offs[d + 1];
    for (int j = e0; j < e1; j++) {
        int s = g_esrc[j];
        float nrm = dv * g_dinv[s];
        float4 v = ((const float4*)(g_h1 + (size_t)s * 128))[lane];
        acc.x += v.x * nrm; acc.y += v.y * nrm;
        acc.z += v.z * nrm; acc.w += v.w * nrm;
    }
    float4 bb = ((const float4*)b1)[lane];
    acc.x = fmaxf(acc.x + bb.x, 0.0f);
    acc.y = fmaxf(acc.y + bb.y, 0.0f);
    acc.z = fmaxf(acc.z + bb.z, 0.0f);
    acc.w = fmaxf(acc.w + bb.w, 0.0f);
    ((float4*)(g_z1 + (size_t)d * 128))[lane] = acc;
}

// ---------------- layer-2 aggregation: warp per dst node, 64 feats ----------------
__global__ void k_agg2(const float* __restrict__ b2) {
    int gw = (blockIdx.x * blockDim.x + threadIdx.x) >> 5;
    int lane = threadIdx.x & 31;
    if (gw >= N_NODES) return;
    int d = gw;
    float dv = g_dinv[d];
    float self = dv * dv;

    float2 h = ((const float2*)(g_h2 + (size_t)d * 64))[lane];
    float2 acc = make_float2(h.x * self, h.y * self);

    int e0 = g_offs[d], e1 = g_offs[d + 1];
    for (int j = e0; j < e1; j++) {
        int s = g_esrc[j];
        float nrm = dv * g_dinv[s];
        float2 v = ((const float2*)(g_h2 + (size_t)s * 64))[lane];
        acc.x += v.x * nrm; acc.y += v.y * nrm;
    }
    float2 bb = ((const float2*)b2)[lane];
    acc.x += bb.x; acc.y += bb.y;
    ((float2*)(g_z2 + (size_t)d * 64))[lane] = acc;
}

// ---------------- decode: warp per edge, dot over 64 feats ----------------
__global__ void k_decode(const int* __restrict__ pos_ei,
                         const int* __restrict__ neg_ei,
                         float* __restrict__ out) {
    int e = (blockIdx.x * blockDim.x + threadIdx.x) >> 5;
    int lane = threadIdx.x & 31;
    if (e >= N_EDGES_TOT) return;
    int a, b;
    if (e < N_POS) { a = pos_ei[e]; b = pos_ei[N_POS + e]; }
    else { int f = e - N_POS; a = neg_ei[f]; b = neg_ei[N_POS + f]; }

    float2 u = ((const float2*)(g_z2 + (size_t)a * 64))[lane];
    float2 v = ((const float2*)(g_z2 + (size_t)b * 64))[lane];
    float s = u.x * v.x + u.y * v.y;
    #pragma unroll
    for (int o = 16; o > 0; o >>= 1) s += __shfl_xor_sync(0xffffffffu, s, o);
    if (lane == 0) out[e] = s;
}

// ---------------- launch ----------------
extern "C" void kernel_launch(void* const* d_in, const int* in_sizes, int n_in,
                              void* d_out, int out_size) {
    const float* x   = (const float*)d_in[0];
    const int*   pos = (const int*)d_in[1];
    const int*   neg = (const int*)d_in[2];
    const float* W1  = (const float*)d_in[3];
    const float* b1  = (const float*)d_in[4];
    const float* W2  = (const float*)d_in[5];
    const float* b2  = (const float*)d_in[6];
    float* out = (float*)d_out;

    const int T = 256;
    k_zero<<<(N_NODES + T - 1) / T, T>>>();
    k_hist<<<(N_POS + T - 1) / T, T>>>(pos);
    k_scanA<<<NB, SCAN_B>>>();
    k_scanB<<<1, 256>>>();
    k_scanC<<<NB, SCAN_B>>>();
    k_fill<<<(N_POS + T - 1) / T, T>>>(pos);

    const int GB = (N_NODES + 127) / 128;   // 782 CTAs

    // GEMM1: h1 = x @ W1 (wmma bf16 3-pass)
    k_wmma1<<<GB, 256>>>(x, W1);
    // agg1 + bias + relu -> z1
    k_agg1<<<(N_NODES * 32 + T - 1) / T, T>>>(b1);
    // GEMM2: h2 = z1 @ W2 (wmma bf16 3-pass)
    k_wmma2<<<GB, 256>>>(W2);
    // agg2 + bias -> z2
    k_agg2<<<(N_NODES * 32 + T - 1) / T, T>>>(b2);
    // decode
    k_decode<<<((size_t)N_EDGES_TOT * 32 + T - 1) / T, T>>>(pos, neg, out);
}

// round 8
// speedup vs baseline: 1.7124x; 1.2508x over previous
#include <cuda_runtime.h>
#include <cuda_bf16.h>
#include <mma.h>
#include <math.h>
#include <stdint.h>

using namespace nvcuda;

#define N_NODES 100000
#define IN_CH   128
#define HIDDEN  128
#define OUT_CH  64
#define N_POS   600000
#define N_EDGES_TOT 1200000

#define SCAN_B 512
#define NB ((N_NODES + SCAN_B - 1) / SCAN_B)   // 196

// ---------------- scratch (no cudaMalloc allowed) ----------------
__device__ float g_h1[(size_t)N_NODES * HIDDEN];   // x @ W1
__device__ float g_z1[(size_t)N_NODES * HIDDEN];   // relu(agg1 + b1)
__device__ float g_h2[(size_t)N_NODES * OUT_CH];   // z1 @ W2
__device__ float g_z2[(size_t)N_NODES * OUT_CH];   // agg2 + b2
__device__ float g_dinv[N_NODES];
__device__ int   g_cnt[N_NODES];
__device__ int   g_cur[N_NODES];
__device__ int   g_offs[N_NODES + 1];
__device__ int   g_esrc[N_POS];
__device__ int   g_bsum[NB];
// pre-converted weights (bf16 hi/lo planes, k-major)
__device__ __nv_bfloat16 gW1h[128 * 128], gW1l[128 * 128];
__device__ __nv_bfloat16 gW2h[128 * 64],  gW2l[128 * 64];

// ---------------- helpers ----------------
__device__ __forceinline__ uint32_t pack2(float a, float b) {
    uint32_t r;
    asm("cvt.rn.satfinite.bf16x2.f32 %0, %1, %2;" : "=r"(r) : "f"(b), "f"(a));
    return r;
}
__device__ __forceinline__ float bf16_round(float v) {
    return __bfloat162float(__float2bfloat16(v));
}

// ---------------- CSR build ----------------
__global__ void k_zero() {
    int i = blockIdx.x * blockDim.x + threadIdx.x;
    if (i < N_NODES) { g_cnt[i] = 0; g_cur[i] = 0; }
}

__global__ void k_hist(const int* __restrict__ pos_ei) {
    int e = blockIdx.x * blockDim.x + threadIdx.x;
    if (e < N_POS) {
        int d = pos_ei[N_POS + e];
        atomicAdd(&g_cnt[d], 1);
    }
}

// convert W1, W2 to bf16 hi/lo planes
__global__ void k_cvtW(const float* __restrict__ W1, const float* __restrict__ W2) {
    int i = blockIdx.x * blockDim.x + threadIdx.x;
    if (i < 128 * 128) {
        float v = W1[i];
        float h = bf16_round(v);
        gW1h[i] = __float2bfloat16(v);
        gW1l[i] = __float2bfloat16(v - h);
    }
    if (i < 128 * 64) {
        float v = W2[i];
        float h = bf16_round(v);
        gW2h[i] = __float2bfloat16(v);
        gW2l[i] = __float2bfloat16(v - h);
    }
}

__global__ __launch_bounds__(SCAN_B) void k_scanA() {
    __shared__ int wsum[16];
    int i = blockIdx.x * SCAN_B + threadIdx.x;
    int lane = threadIdx.x & 31, wid = threadIdx.x >> 5;
    int v = (i < N_NODES) ? g_cnt[i] : 0;
    if (i < N_NODES) g_dinv[i] = rsqrtf((float)v + 1.0f);

    int s = v;
    #pragma unroll
    for (int o = 1; o < 32; o <<= 1) {
        int t = __shfl_up_sync(0xffffffffu, s, o);
        if (lane >= o) s += t;
    }
    if (lane == 31) wsum[wid] = s;
    __syncthreads();
    if (wid == 0) {
        int w = (lane < 16) ? wsum[lane] : 0;
        #pragma unroll
        for (int o = 1; o < 16; o <<= 1) {
            int t = __shfl_up_sync(0xffffffffu, w, o);
            if (lane >= o) w += t;
        }
        if (lane < 16) wsum[lane] = w;
    }
    __syncthreads();
    int excl = s - v + (wid > 0 ? wsum[wid - 1] : 0);
    if (i < N_NODES) g_offs[i] = excl;
    if (threadIdx.x == 0) g_bsum[blockIdx.x] = wsum[15];
}

__global__ __launch_bounds__(256) void k_scanB() {
    __shared__ int wsum[8];
    int lane = threadIdx.x & 31, wid = threadIdx.x >> 5;
    int v = (threadIdx.x < NB) ? g_bsum[threadIdx.x] : 0;
    int s = v;
    #pragma unroll
    for (int o = 1; o < 32; o <<= 1) {
        int t = __shfl_up_sync(0xffffffffu, s, o);
        if (lane >= o) s += t;
    }
    if (lane == 31) wsum[wid] = s;
    __syncthreads();
    if (wid == 0) {
        int w = (lane < 8) ? wsum[lane] : 0;
        #pragma unroll
        for (int o = 1; o < 8; o <<= 1) {
            int t = __shfl_up_sync(0xffffffffu, w, o);
            if (lane >= o) w += t;
        }
        if (lane < 8) wsum[lane] = w;
    }
    __syncthreads();
    int excl = s - v + (wid > 0 ? wsum[wid - 1] : 0);
    if (threadIdx.x < NB) g_bsum[threadIdx.x] = excl;
    if (threadIdx.x == NB - 1) g_offs[N_NODES] = excl + v;
}

__global__ __launch_bounds__(SCAN_B) void k_scanC() {
    int i = blockIdx.x * SCAN_B + threadIdx.x;
    if (i < N_NODES) g_offs[i] += g_bsum[blockIdx.x];
}

__global__ void k_fill(const int* __restrict__ pos_ei) {
    int e = blockIdx.x * blockDim.x + threadIdx.x;
    if (e < N_POS) {
        int s = pos_ei[e];
        int d = pos_ei[N_POS + e];
        int p = g_offs[d] + atomicAdd(&g_cur[d], 1);
        g_esrc[p] = s;
    }
}

// =================================================================
// WMMA GEMM body: C[nrows][OUTC] = A[nrows][128] @ W[128][OUTC]
// bf16 hi/lo 3-pass split. W pre-converted (global bf16 planes).
// 256 threads = 8 warps x 16 rows = 128 rows/CTA. K staged in 32-chunks.
// =================================================================
#define SA 48   // A smem stride (elems)

template <int OUTC>
__device__ __forceinline__ void wmma_body(const float* __restrict__ A,
                                          const __nv_bfloat16* __restrict__ Wh,
                                          const __nv_bfloat16* __restrict__ Wl,
                                          float* __restrict__ C, int nrows) {
    constexpr int SW = OUTC + 16;
    __shared__ alignas(256) __nv_bfloat16 sAh[128 * SA];
    __shared__ alignas(256) __nv_bfloat16 sAl[128 * SA];
    __shared__ alignas(256) __nv_bfloat16 sWh[32 * SW];
    __shared__ alignas(256) __nv_bfloat16 sWl[32 * SW];

    const int tid  = threadIdx.x;
    const int warp = tid >> 5;
    const int row0 = blockIdx.x * 128;

    constexpr int NT = OUTC / 16;
    wmma::fragment<wmma::accumulator, 16, 16, 16, float> acc[NT];
    #pragma unroll
    for (int nt = 0; nt < NT; nt++) wmma::fill_fragment(acc[nt], 0.0f);

    for (int kb = 0; kb < 128; kb += 32) {
        // ---- stage A chunk [128 x 32] as bf16 hi/lo (convert) ----
        for (int idx = tid * 4; idx < 128 * 32; idx += 1024) {
            int r = idx >> 5, c = idx & 31;
            int grow = row0 + r;
            float4 v = make_float4(0.f, 0.f, 0.f, 0.f);
            if (grow < nrows) v = *(const float4*)(A + (size_t)grow * 128 + kb + c);
            uint32_t h0 = pack2(v.x, v.y), h1 = pack2(v.z, v.w);
            uint32_t l0 = pack2(v.x - bf16_round(v.x), v.y - bf16_round(v.y));
            uint32_t l1 = pack2(v.z - bf16_round(v.z), v.w - bf16_round(v.w));
            *(uint2*)(sAh + r * SA + c) = make_uint2(h0, h1);
            *(uint2*)(sAl + r * SA + c) = make_uint2(l0, l1);
        }
        // ---- stage W chunk [32 x OUTC]: pure vector copy of bf16 planes ----
        for (int idx = tid * 8; idx < 32 * OUTC; idx += 2048) {
            int kr = idx / OUTC, n = idx % OUTC;
            *(uint4*)(sWh + kr * SW + n) = *(const uint4*)(Wh + (size_t)(kb + kr) * OUTC + n);
            *(uint4*)(sWl + kr * SW + n) = *(const uint4*)(Wl + (size_t)(kb + kr) * OUTC + n);
        }
        __syncthreads();

        #pragma unroll
        for (int kk = 0; kk < 32; kk += 16) {
            wmma::fragment<wmma::matrix_a, 16, 16, 16, __nv_bfloat16, wmma::row_major> fah, fal;
            wmma::load_matrix_sync(fah, sAh + warp * 16 * SA + kk, SA);
            wmma::load_matrix_sync(fal, sAl + warp * 16 * SA + kk, SA);
            #pragma unroll
            for (int nt = 0; nt < NT; nt++) {
                wmma::fragment<wmma::matrix_b, 16, 16, 16, __nv_bfloat16, wmma::row_major> fbh, fbl;
                wmma::load_matrix_sync(fbh, sWh + kk * SW + nt * 16, SW);
                wmma::load_matrix_sync(fbl, sWl + kk * SW + nt * 16, SW);
                wmma::mma_sync(acc[nt], fah, fbh, acc[nt]);
                wmma::mma_sync(acc[nt], fah, fbl, acc[nt]);
                wmma::mma_sync(acc[nt], fal, fbh, acc[nt]);
            }
        }
        __syncthreads();
    }

    int wr = row0 + warp * 16;
    if (wr + 16 <= nrows) {
        #pragma unroll
        for (int nt = 0; nt < NT; nt++)
            wmma::store_matrix_sync(C + (size_t)wr * OUTC + nt * 16, acc[nt],
                                    OUTC, wmma::mem_row_major);
    }
}

// wrapper kernels: device-side references to the __device__ globals
__global__ __launch_bounds__(256) void k_wmma1(const float* __restrict__ x) {
    wmma_body<128>(x, gW1h, gW1l, g_h1, N_NODES);
}
__global__ __launch_bounds__(256) void k_wmma2() {
    wmma_body<64>(g_z1, gW2h, gW2l, g_h2, N_NODES);
}

// ---------------- layer-1 aggregation: warp per dst node, 128 feats ----------------
__global__ void k_agg1(const float* __restrict__ b1) {
    int gw = (blockIdx.x * blockDim.x + threadIdx.x) >> 5;
    int lane = threadIdx.x & 31;
    if (gw >= N_NODES) return;
    int d = gw;
    float dv = g_dinv[d];
    float self = dv * dv;

    float4 h = ((const float4*)(g_h1 + (size_t)d * 128))[lane];
    float4 acc = make_float4(h.x * self, h.y * self, h.z * self, h.w * self);

    int e0 = g_offs[d], e1 = g_offs[d + 1];
    int j = e0;
    for (; j + 2 <= e1; j += 2) {
        int s0 = g_esrc[j], s1 = g_esrc[j + 1];
        float n0 = dv * g_dinv[s0];
        float n1 = dv * g_dinv[s1];
        float4 v0 = ((const float4*)(g_h1 + (size_t)s0 * 128))[lane];
        float4 v1 = ((const float4*)(g_h1 + (size_t)s1 * 128))[lane];
        acc.x += v0.x * n0 + v1.x * n1;
        acc.y += v0.y * n0 + v1.y * n1;
        acc.z += v0.z * n0 + v1.z * n1;
        acc.w += v0.w * n0 + v1.w * n1;
    }
    if (j < e1) {
        int s0 = g_esrc[j];
        float n0 = dv * g_dinv[s0];
        float4 v0 = ((const float4*)(g_h1 + (size_t)s0 * 128))[lane];
        acc.x += v0.x * n0; acc.y += v0.y * n0;
        acc.z += v0.z * n0; acc.w += v0.w * n0;
    }
    float4 bb = ((const float4*)b1)[lane];
    acc.x = fmaxf(acc.x + bb.x, 0.0f);
    acc.y = fmaxf(acc.y + bb.y, 0.0f);
    acc.z = fmaxf(acc.z + bb.z, 0.0f);
    acc.w = fmaxf(acc.w + bb.w, 0.0f);
    ((float4*)(g_z1 + (size_t)d * 128))[lane] = acc;
}

// ---------------- layer-2 aggregation: warp per dst node, 64 feats ----------------
__global__ void k_agg2(const float* __restrict__ b2) {
    int gw = (blockIdx.x * blockDim.x + threadIdx.x) >> 5;
    int lane = threadIdx.x & 31;
    if (gw >= N_NODES) return;
    int d = gw;
    float dv = g_dinv[d];
    float self = dv * dv;

    float2 h = ((const float2*)(g_h2 + (size_t)d * 64))[lane];
    float2 acc = make_float2(h.x * self, h.y * self);

    int e0 = g_offs[d], e1 = g_offs[d + 1];
    int j = e0;
    for (; j + 2 <= e1; j += 2) {
        int s0 = g_esrc[j], s1 = g_esrc[j + 1];
        float n0 = dv * g_dinv[s0];
        float n1 = dv * g_dinv[s1];
        float2 v0 = ((const float2*)(g_h2 + (size_t)s0 * 64))[lane];
        float2 v1 = ((const float2*)(g_h2 + (size_t)s1 * 64))[lane];
        acc.x += v0.x * n0 + v1.x * n1;
        acc.y += v0.y * n0 + v1.y * n1;
    }
    if (j < e1) {
        int s0 = g_esrc[j];
        float n0 = dv * g_dinv[s0];
        float2 v0 = ((const float2*)(g_h2 + (size_t)s0 * 64))[lane];
        acc.x += v0.x * n0; acc.y += v0.y * n0;
    }
    float2 bb = ((const float2*)b2)[lane];
    acc.x += bb.x; acc.y += bb.y;
    ((float2*)(g_z2 + (size_t)d * 64))[lane] = acc;
}

// ---------------- decode: warp per 2 edges, dot over 64 feats ----------------
__global__ void k_decode(const int* __restrict__ pos_ei,
                         const int* __restrict__ neg_ei,
                         float* __restrict__ out) {
    int w = (blockIdx.x * blockDim.x + threadIdx.x) >> 5;
    int lane = threadIdx.x & 31;
    int ea = w * 2;
    if (ea >= N_EDGES_TOT) return;
    int eb = ea + 1;
    bool has_b = (eb < N_EDGES_TOT);

    int a0, b0, a1 = 0, b1 = 0;
    if (ea < N_POS) { a0 = pos_ei[ea]; b0 = pos_ei[N_POS + ea]; }
    else { int f = ea - N_POS; a0 = neg_ei[f]; b0 = neg_ei[N_POS + f]; }
    if (has_b) {
        if (eb < N_POS) { a1 = pos_ei[eb]; b1 = pos_ei[N_POS + eb]; }
        else { int f = eb - N_POS; a1 = neg_ei[f]; b1 = neg_ei[N_POS + f]; }
    }

    float2 u0 = ((const float2*)(g_z2 + (size_t)a0 * 64))[lane];
    float2 v0 = ((const float2*)(g_z2 + (size_t)b0 * 64))[lane];
    float2 u1 = make_float2(0.f, 0.f), v1 = make_float2(0.f, 0.f);
    if (has_b) {
        u1 = ((const float2*)(g_z2 + (size_t)a1 * 64))[lane];
        v1 = ((const float2*)(g_z2 + (size_t)b1 * 64))[lane];
    }
    float s0 = u0.x * v0.x + u0.y * v0.y;
    float s1 = u1.x * v1.x + u1.y * v1.y;
    #pragma unroll
    for (int o = 16; o > 0; o >>= 1) {
        s0 += __shfl_xor_sync(0xffffffffu, s0, o);
        s1 += __shfl_xor_sync(0xffffffffu, s1, o);
    }
    if (lane == 0) {
        out[ea] = s0;
        if (has_b) out[eb] = s1;
    }
}

// ---------------- launch ----------------
extern "C" void kernel_launch(void* const* d_in, const int* in_sizes, int n_in,
                              void* d_out, int out_size) {
    const float* x   = (const float*)d_in[0];
    const int*   pos = (const int*)d_in[1];
    const int*   neg = (const int*)d_in[2];
    const float* W1  = (const float*)d_in[3];
    const float* b1  = (const float*)d_in[4];
    const float* W2  = (const float*)d_in[5];
    const float* b2  = (const float*)d_in[6];
    float* out = (float*)d_out;

    const int T = 256;
    const int GB = (N_NODES + 127) / 128;   // 782 CTAs

    // order chosen so launch #4 (ncu capture slot) is k_wmma1
    k_zero<<<(N_NODES + T - 1) / T, T>>>();                       // 1
    k_hist<<<(N_POS + T - 1) / T, T>>>(pos);                      // 2
    k_cvtW<<<(128 * 128 + T - 1) / T, T>>>(W1, W2);               // 3
    k_wmma1<<<GB, 256>>>(x);                                      // 4  <- profiled
    k_scanA<<<NB, SCAN_B>>>();                                    // 5
    k_scanB<<<1, 256>>>();                                        // 6
    k_scanC<<<NB, SCAN_B>>>();                                    // 7
    k_fill<<<(N_POS + T - 1) / T, T>>>(pos);                      // 8
    k_agg1<<<(N_NODES * 32 + T - 1) / T, T>>>(b1);                // 9
    k_wmma2<<<GB, 256>>>();                                       // 10
    k_agg2<<<(N_NODES * 32 + T - 1) / T, T>>>(b2);                // 11
    k_decode<<<((size_t)(N_EDGES_TOT / 2 + 1) * 32 + T - 1) / T, T>>>(pos, neg, out); // 12
}

// round 9
// speedup vs baseline: 1.7381x; 1.0150x over previous
#include <cuda_runtime.h>
#include <cuda_bf16.h>
#include <mma.h>
#include <math.h>
#include <stdint.h>

using namespace nvcuda;

#define N_NODES 100000
#define IN_CH   128
#define HIDDEN  128
#define OUT_CH  64
#define N_POS   600000
#define N_EDGES_TOT 1200000

#define SCAN_B 512
#define NB ((N_NODES + SCAN_B - 1) / SCAN_B)   // 196

// ---------------- scratch (no cudaMalloc allowed) ----------------
__device__ float g_h1[(size_t)N_NODES * HIDDEN];   // x @ W1
__device__ float g_z1[(size_t)N_NODES * HIDDEN];   // relu(agg1 + b1)
__device__ float g_h2[(size_t)N_NODES * OUT_CH];   // z1 @ W2
__device__ float g_z2[(size_t)N_NODES * OUT_CH];   // agg2 + b2
__device__ float g_dinv[N_NODES];
__device__ int   g_cnt[N_NODES];
__device__ int   g_cur[N_NODES];
__device__ int   g_offs[N_NODES + 1];
__device__ int   g_esrc[N_POS];
__device__ int   g_bsum[NB];
// pre-converted weights (bf16 hi/lo planes, k-major)
__device__ __nv_bfloat16 gW1h[128 * 128], gW1l[128 * 128];
__device__ __nv_bfloat16 gW2h[128 * 64],  gW2l[128 * 64];

// ---------------- helpers ----------------
__device__ __forceinline__ uint32_t pack2(float a, float b) {
    uint32_t r;
    asm("cvt.rn.satfinite.bf16x2.f32 %0, %1, %2;" : "=r"(r) : "f"(b), "f"(a));
    return r;
}
__device__ __forceinline__ float bf16_round(float v) {
    return __bfloat162float(__float2bfloat16(v));
}

// ---------------- CSR build ----------------
__global__ void k_zero() {
    int i = blockIdx.x * blockDim.x + threadIdx.x;
    if (i < N_NODES) { g_cnt[i] = 0; g_cur[i] = 0; }
}

__global__ void k_hist(const int* __restrict__ pos_ei) {
    int e = blockIdx.x * blockDim.x + threadIdx.x;
    if (e < N_POS) {
        int d = pos_ei[N_POS + e];
        atomicAdd(&g_cnt[d], 1);
    }
}

// convert W1, W2 to bf16 hi/lo planes
__global__ void k_cvtW(const float* __restrict__ W1, const float* __restrict__ W2) {
    int i = blockIdx.x * blockDim.x + threadIdx.x;
    if (i < 128 * 128) {
        float v = W1[i];
        float h = bf16_round(v);
        gW1h[i] = __float2bfloat16(v);
        gW1l[i] = __float2bfloat16(v - h);
    }
    if (i < 128 * 64) {
        float v = W2[i];
        float h = bf16_round(v);
        gW2h[i] = __float2bfloat16(v);
        gW2l[i] = __float2bfloat16(v - h);
    }
}

__global__ __launch_bounds__(SCAN_B) void k_scanA() {
    __shared__ int wsum[16];
    int i = blockIdx.x * SCAN_B + threadIdx.x;
    int lane = threadIdx.x & 31, wid = threadIdx.x >> 5;
    int v = (i < N_NODES) ? g_cnt[i] : 0;
    if (i < N_NODES) g_dinv[i] = rsqrtf((float)v + 1.0f);

    int s = v;
    #pragma unroll
    for (int o = 1; o < 32; o <<= 1) {
        int t = __shfl_up_sync(0xffffffffu, s, o);
        if (lane >= o) s += t;
    }
    if (lane == 31) wsum[wid] = s;
    __syncthreads();
    if (wid == 0) {
        int w = (lane < 16) ? wsum[lane] : 0;
        #pragma unroll
        for (int o = 1; o < 16; o <<= 1) {
            int t = __shfl_up_sync(0xffffffffu, w, o);
            if (lane >= o) w += t;
        }
        if (lane < 16) wsum[lane] = w;
    }
    __syncthreads();
    int excl = s - v + (wid > 0 ? wsum[wid - 1] : 0);
    if (i < N_NODES) g_offs[i] = excl;
    if (threadIdx.x == 0) g_bsum[blockIdx.x] = wsum[15];
}

__global__ __launch_bounds__(256) void k_scanB() {
    __shared__ int wsum[8];
    int lane = threadIdx.x & 31, wid = threadIdx.x >> 5;
    int v = (threadIdx.x < NB) ? g_bsum[threadIdx.x] : 0;
    int s = v;
    #pragma unroll
    for (int o = 1; o < 32; o <<= 1) {
        int t = __shfl_up_sync(0xffffffffu, s, o);
        if (lane >= o) s += t;
    }
    if (lane == 31) wsum[wid] = s;
    __syncthreads();
    if (wid == 0) {
        int w = (lane < 8) ? wsum[lane] : 0;
        #pragma unroll
        for (int o = 1; o < 8; o <<= 1) {
            int t = __shfl_up_sync(0xffffffffu, w, o);
            if (lane >= o) w += t;
        }
        if (lane < 8) wsum[lane] = w;
    }
    __syncthreads();
    int excl = s - v + (wid > 0 ? wsum[wid - 1] : 0);
    if (threadIdx.x < NB) g_bsum[threadIdx.x] = excl;
    if (threadIdx.x == NB - 1) g_offs[N_NODES] = excl + v;
}

__global__ __launch_bounds__(SCAN_B) void k_scanC() {
    int i = blockIdx.x * SCAN_B + threadIdx.x;
    if (i < N_NODES) g_offs[i] += g_bsum[blockIdx.x];
}

__global__ void k_fill(const int* __restrict__ pos_ei) {
    int e = blockIdx.x * blockDim.x + threadIdx.x;
    if (e < N_POS) {
        int s = pos_ei[e];
        int d = pos_ei[N_POS + e];
        int p = g_offs[d] + atomicAdd(&g_cur[d], 1);
        g_esrc[p] = s;
    }
}

// =================================================================
// WMMA GEMM body: computes a 64-column tile of
//   C[nrows][OUTC] = A[nrows][128] @ W[128][OUTC]
// column tile selected by blockIdx.y. bf16 hi/lo 3-pass split.
// 256 threads = 8 warps x 16 rows = 128 rows/CTA. K staged in 32-chunks.
// NT=4 accumulators -> ~70 regs -> 3 CTAs/SM (vs 2 at NT=8).
// =================================================================
#define SA 48            // A smem stride (elems)
#define CTILE 64         // columns per CTA
#define SWS (CTILE + 16) // W smem stride

template <int OUTC>
__device__ __forceinline__ void wmma_body(const float* __restrict__ A,
                                          const __nv_bfloat16* __restrict__ Wh,
                                          const __nv_bfloat16* __restrict__ Wl,
                                          float* __restrict__ C, int nrows) {
    __shared__ alignas(256) __nv_bfloat16 sAh[128 * SA];
    __shared__ alignas(256) __nv_bfloat16 sAl[128 * SA];
    __shared__ alignas(256) __nv_bfloat16 sWh[32 * SWS];
    __shared__ alignas(256) __nv_bfloat16 sWl[32 * SWS];

    const int tid  = threadIdx.x;
    const int warp = tid >> 5;
    const int row0 = blockIdx.x * 128;
    const int col0 = blockIdx.y * CTILE;

    constexpr int NT = CTILE / 16;   // 4
    wmma::fragment<wmma::accumulator, 16, 16, 16, float> acc[NT];
    #pragma unroll
    for (int nt = 0; nt < NT; nt++) wmma::fill_fragment(acc[nt], 0.0f);

    for (int kb = 0; kb < 128; kb += 32) {
        // ---- stage A chunk [128 x 32] as bf16 hi/lo (convert) ----
        for (int idx = tid * 4; idx < 128 * 32; idx += 1024) {
            int r = idx >> 5, c = idx & 31;
            int grow = row0 + r;
            float4 v = make_float4(0.f, 0.f, 0.f, 0.f);
            if (grow < nrows) v = *(const float4*)(A + (size_t)grow * 128 + kb + c);
            uint32_t h0 = pack2(v.x, v.y), h1 = pack2(v.z, v.w);
            uint32_t l0 = pack2(v.x - bf16_round(v.x), v.y - bf16_round(v.y));
            uint32_t l1 = pack2(v.z - bf16_round(v.z), v.w - bf16_round(v.w));
            *(uint2*)(sAh + r * SA + c) = make_uint2(h0, h1);
            *(uint2*)(sAl + r * SA + c) = make_uint2(l0, l1);
        }
        // ---- stage W chunk [32 x CTILE]: pure vector copy of bf16 planes ----
        for (int idx = tid * 8; idx < 32 * CTILE; idx += 2048) {
            int kr = idx / CTILE, n = idx % CTILE;
            *(uint4*)(sWh + kr * SWS + n) =
                *(const uint4*)(Wh + (size_t)(kb + kr) * OUTC + col0 + n);
            *(uint4*)(sWl + kr * SWS + n) =
                *(const uint4*)(Wl + (size_t)(kb + kr) * OUTC + col0 + n);
        }
        __syncthreads();

        #pragma unroll
        for (int kk = 0; kk < 32; kk += 16) {
            wmma::fragment<wmma::matrix_a, 16, 16, 16, __nv_bfloat16, wmma::row_major> fah, fal;
            wmma::load_matrix_sync(fah, sAh + warp * 16 * SA + kk, SA);
            wmma::load_matrix_sync(fal, sAl + warp * 16 * SA + kk, SA);
            #pragma unroll
            for (int nt = 0; nt < NT; nt++) {
                wmma::fragment<wmma::matrix_b, 16, 16, 16, __nv_bfloat16, wmma::row_major> fbh, fbl;
                wmma::load_matrix_sync(fbh, sWh + kk * SWS + nt * 16, SWS);
                wmma::load_matrix_sync(fbl, sWl + kk * SWS + nt * 16, SWS);
                wmma::mma_sync(acc[nt], fah, fbh, acc[nt]);
                wmma::mma_sync(acc[nt], fah, fbl, acc[nt]);
                wmma::mma_sync(acc[nt], fal, fbh, acc[nt]);
            }
        }
        __syncthreads();
    }

    int wr = row0 + warp * 16;
    if (wr + 16 <= nrows) {
        #pragma unroll
        for (int nt = 0; nt < NT; nt++)
            wmma::store_matrix_sync(C + (size_t)wr * OUTC + col0 + nt * 16, acc[nt],
                                    OUTC, wmma::mem_row_major);
    }
}

// wrapper kernels: device-side references to the __device__ globals
__global__ __launch_bounds__(256) void k_wmma1(const float* __restrict__ x) {
    wmma_body<128>(x, gW1h, gW1l, g_h1, N_NODES);
}
__global__ __launch_bounds__(256) void k_wmma2() {
    wmma_body<64>(g_z1, gW2h, gW2l, g_h2, N_NODES);
}

// ---------------- layer-1 aggregation: warp per dst node, 128 feats ----------------
__global__ void k_agg1(const float* __restrict__ b1) {
    int gw = (blockIdx.x * blockDim.x + threadIdx.x) >> 5;
    int lane = threadIdx.x & 31;
    if (gw >= N_NODES) return;
    int d = gw;
    float dv = g_dinv[d];
    float self = dv * dv;

    float4 h = ((const float4*)(g_h1 + (size_t)d * 128))[lane];
    float4 acc = make_float4(h.x * self, h.y * self, h.z * self, h.w * self);

    int e0 = g_offs[d], e1 = g_offs[d + 1];
    int j = e0;
    for (; j + 4 <= e1; j += 4) {
        int s0 = g_esrc[j], s1 = g_esrc[j + 1], s2 = g_esrc[j + 2], s3 = g_esrc[j + 3];
        float n0 = dv * g_dinv[s0];
        float n1 = dv * g_dinv[s1];
        float n2 = dv * g_dinv[s2];
        float n3 = dv * g_dinv[s3];
        float4 v0 = ((const float4*)(g_h1 + (size_t)s0 * 128))[lane];
        float4 v1 = ((const float4*)(g_h1 + (size_t)s1 * 128))[lane];
        float4 v2 = ((const float4*)(g_h1 + (size_t)s2 * 128))[lane];
        float4 v3 = ((const float4*)(g_h1 + (size_t)s3 * 128))[lane];
        acc.x += v0.x * n0 + v1.x * n1 + v2.x * n2 + v3.x * n3;
        acc.y += v0.y * n0 + v1.y * n1 + v2.y * n2 + v3.y * n3;
        acc.z += v0.z * n0 + v1.z * n1 + v2.z * n2 + v3.z * n3;
        acc.w += v0.w * n0 + v1.w * n1 + v2.w * n2 + v3.w * n3;
    }
    for (; j < e1; j++) {
        int s0 = g_esrc[j];
        float n0 = dv * g_dinv[s0];
        float4 v0 = ((const float4*)(g_h1 + (size_t)s0 * 128))[lane];
        acc.x += v0.x * n0; acc.y += v0.y * n0;
        acc.z += v0.z * n0; acc.w += v0.w * n0;
    }
    float4 bb = ((const float4*)b1)[lane];
    acc.x = fmaxf(acc.x + bb.x, 0.0f);
    acc.y = fmaxf(acc.y + bb.y, 0.0f);
    acc.z = fmaxf(acc.z + bb.z, 0.0f);
    acc.w = fmaxf(acc.w + bb.w, 0.0f);
    ((float4*)(g_z1 + (size_t)d * 128))[lane] = acc;
}

// ---------------- layer-2 aggregation: warp per dst node, 64 feats ----------------
__global__ void k_agg2(const float* __restrict__ b2) {
    int gw = (blockIdx.x * blockDim.x + threadIdx.x) >> 5;
    int lane = threadIdx.x & 31;
    if (gw >= N_NODES) return;
    int d = gw;
    float dv = g_dinv[d];
    float self = dv * dv;

    float2 h = ((const float2*)(g_h2 + (size_t)d * 64))[lane];
    float2 acc = make_float2(h.x * self, h.y * self);

    int e0 = g_offs[d], e1 = g_offs[d + 1];
    int j = e0;
    for (; j + 4 <= e1; j += 4) {
        int s0 = g_esrc[j], s1 = g_esrc[j + 1], s2 = g_esrc[j + 2], s3 = g_esrc[j + 3];
        float n0 = dv * g_dinv[s0];
        float n1 = dv * g_dinv[s1];
        float n2 = dv * g_dinv[s2];
        float n3 = dv * g_dinv[s3];
        float2 v0 = ((const float2*)(g_h2 + (size_t)s0 * 64))[lane];
        float2 v1 = ((const float2*)(g_h2 + (size_t)s1 * 64))[lane];
        float2 v2 = ((const float2*)(g_h2 + (size_t)s2 * 64))[lane];
        float2 v3 = ((const float2*)(g_h2 + (size_t)s3 * 64))[lane];
        acc.x += v0.x * n0 + v1.x * n1 + v2.x * n2 + v3.x * n3;
        acc.y += v0.y * n0 + v1.y * n1 + v2.y * n2 + v3.y * n3;
    }
    for (; j < e1; j++) {
        int s0 = g_esrc[j];
        float n0 = dv * g_dinv[s0];
        float2 v0 = ((const float2*)(g_h2 + (size_t)s0 * 64))[lane];
        acc.x += v0.x * n0; acc.y += v0.y * n0;
    }
    float2 bb = ((const float2*)b2)[lane];
    acc.x += bb.x; acc.y += bb.y;
    ((float2*)(g_z2 + (size_t)d * 64))[lane] = acc;
}

// ---------------- decode: warp per 2 edges, dot over 64 feats ----------------
__global__ void k_decode(const int* __restrict__ pos_ei,
                         const int* __restrict__ neg_ei,
                         float* __restrict__ out) {
    int w = (blockIdx.x * blockDim.x + threadIdx.x) >> 5;
    int lane = threadIdx.x & 31;
    int ea = w * 2;
    if (ea >= N_EDGES_TOT) return;
    int eb = ea + 1;
    bool has_b = (eb < N_EDGES_TOT);

    int a0, b0, a1 = 0, b1 = 0;
    if (ea < N_POS) { a0 = pos_ei[ea]; b0 = pos_ei[N_POS + ea]; }
    else { int f = ea - N_POS; a0 = neg_ei[f]; b0 = neg_ei[N_POS + f]; }
    if (has_b) {
        if (eb < N_POS) { a1 = pos_ei[eb]; b1 = pos_ei[N_POS + eb]; }
        else { int f = eb - N_POS; a1 = neg_ei[f]; b1 = neg_ei[N_POS + f]; }
    }

    float2 u0 = ((const float2*)(g_z2 + (size_t)a0 * 64))[lane];
    float2 v0 = ((const float2*)(g_z2 + (size_t)b0 * 64))[lane];
    float2 u1 = make_float2(0.f, 0.f), v1 = make_float2(0.f, 0.f);
    if (has_b) {
        u1 = ((const float2*)(g_z2 + (size_t)a1 * 64))[lane];
        v1 = ((const float2*)(g_z2 + (size_t)b1 * 64))[lane];
    }
    float s0 = u0.x * v0.x + u0.y * v0.y;
    float s1 = u1.x * v1.x + u1.y * v1.y;
    #pragma unroll
    for (int o = 16; o > 0; o >>= 1) {
        s0 += __shfl_xor_sync(0xffffffffu, s0, o);
        s1 += __shfl_xor_sync(0xffffffffu, s1, o);
    }
    if (lane == 0) {
        out[ea] = s0;
        if (has_b) out[eb] = s1;
    }
}

// ---------------- launch ----------------
extern "C" void kernel_launch(void* const* d_in, const int* in_sizes, int n_in,
                              void* d_out, int out_size) {
    const float* x   = (const float*)d_in[0];
    const int*   pos = (const int*)d_in[1];
    const int*   neg = (const int*)d_in[2];
    const float* W1  = (const float*)d_in[3];
    const float* b1  = (const float*)d_in[4];
    const float* W2  = (const float*)d_in[5];
    const float* b2  = (const float*)d_in[6];
    float* out = (float*)d_out;

    const int T = 256;
    const int GB = (N_NODES + 127) / 128;   // 782 row blocks

    // order chosen so launch #4 (ncu capture slot) is k_wmma1
    k_zero<<<(N_NODES + T - 1) / T, T>>>();                       // 1
    k_hist<<<(N_POS + T - 1) / T, T>>>(pos);                      // 2
    k_cvtW<<<(128 * 128 + T - 1) / T, T>>>(W1, W2);               // 3
    k_wmma1<<<dim3(GB, 2), 256>>>(x);                             // 4  <- profiled
    k_scanA<<<NB, SCAN_B>>>();                                    // 5
    k_scanB<<<1, 256>>>();                                        // 6
    k_scanC<<<NB, SCAN_B>>>();                                    // 7
    k_fill<<<(N_POS + T - 1) / T, T>>>(pos);                      // 8
    k_agg1<<<(N_NODES * 32 + T - 1) / T, T>>>(b1);                // 9
    k_wmma2<<<dim3(GB, 1), 256>>>();                              // 10
    k_agg2<<<(N_NODES * 32 + T - 1) / T, T>>>(b2);                // 11
    k_decode<<<((size_t)(N_EDGES_TOT / 2 + 1) * 32 + T - 1) / T, T>>>(pos, neg, out); // 12
}

// round 10
// speedup vs baseline: 1.8144x; 1.0439x over previous
#include <cuda_runtime.h>
#include <cuda_bf16.h>
#include <mma.h>
#include <math.h>
#include <stdint.h>

using namespace nvcuda;

#define N_NODES 100000
#define IN_CH   128
#define HIDDEN  128
#define OUT_CH  64
#define N_POS   600000
#define N_EDGES_TOT 1200000

#define SCAN_B 512
#define NB ((N_NODES + SCAN_B - 1) / SCAN_B)   // 196

// ---------------- scratch (no cudaMalloc allowed) ----------------
__device__ float g_h1[(size_t)N_NODES * HIDDEN];   // x @ W1
__device__ float g_z1[(size_t)N_NODES * HIDDEN];   // relu(agg1 + b1)
__device__ float g_h2[(size_t)N_NODES * OUT_CH];   // z1 @ W2
__device__ float g_z2[(size_t)N_NODES * OUT_CH];   // agg2 + b2
__device__ float g_dinv[N_NODES];
__device__ int   g_cnt[N_NODES];
__device__ int   g_cur[N_NODES];
__device__ int   g_offs[N_NODES + 1];
__device__ int   g_esrc[N_POS];
__device__ int   g_bsum[NB];
// pre-converted weights (bf16 hi/lo planes, k-major)
__device__ __nv_bfloat16 gW1h[128 * 128], gW1l[128 * 128];
__device__ __nv_bfloat16 gW2h[128 * 64],  gW2l[128 * 64];

// ---------------- helpers ----------------
__device__ __forceinline__ uint32_t pack2(float a, float b) {
    uint32_t r;
    asm("cvt.rn.satfinite.bf16x2.f32 %0, %1, %2;" : "=r"(r) : "f"(b), "f"(a));
    return r;
}
__device__ __forceinline__ float bf16_round(float v) {
    return __bfloat162float(__float2bfloat16(v));
}

// ---------------- CSR build ----------------
__global__ void k_zero() {
    int i = blockIdx.x * blockDim.x + threadIdx.x;
    if (i < N_NODES) { g_cnt[i] = 0; g_cur[i] = 0; }
}

__global__ void k_hist(const int* __restrict__ pos_ei) {
    int e = blockIdx.x * blockDim.x + threadIdx.x;
    if (e < N_POS) {
        int d = pos_ei[N_POS + e];
        atomicAdd(&g_cnt[d], 1);
    }
}

// convert W1, W2 to bf16 hi/lo planes
__global__ void k_cvtW(const float* __restrict__ W1, const float* __restrict__ W2) {
    int i = blockIdx.x * blockDim.x + threadIdx.x;
    if (i < 128 * 128) {
        float v = W1[i];
        float h = bf16_round(v);
        gW1h[i] = __float2bfloat16(v);
        gW1l[i] = __float2bfloat16(v - h);
    }
    if (i < 128 * 64) {
        float v = W2[i];
        float h = bf16_round(v);
        gW2h[i] = __float2bfloat16(v);
        gW2l[i] = __float2bfloat16(v - h);
    }
}

__global__ __launch_bounds__(SCAN_B) void k_scanA() {
    __shared__ int wsum[16];
    int i = blockIdx.x * SCAN_B + threadIdx.x;
    int lane = threadIdx.x & 31, wid = threadIdx.x >> 5;
    int v = (i < N_NODES) ? g_cnt[i] : 0;
    if (i < N_NODES) g_dinv[i] = rsqrtf((float)v + 1.0f);

    int s = v;
    #pragma unroll
    for (int o = 1; o < 32; o <<= 1) {
        int t = __shfl_up_sync(0xffffffffu, s, o);
        if (lane >= o) s += t;
    }
    if (lane == 31) wsum[wid] = s;
    __syncthreads();
    if (wid == 0) {
        int w = (lane < 16) ? wsum[lane] : 0;
        #pragma unroll
        for (int o = 1; o < 16; o <<= 1) {
            int t = __shfl_up_sync(0xffffffffu, w, o);
            if (lane >= o) w += t;
        }
        if (lane < 16) wsum[lane] = w;
    }
    __syncthreads();
    int excl = s - v + (wid > 0 ? wsum[wid - 1] : 0);
    if (i < N_NODES) g_offs[i] = excl;
    if (threadIdx.x == 0) g_bsum[blockIdx.x] = wsum[15];
}

__global__ __launch_bounds__(256) void k_scanB() {
    __shared__ int wsum[8];
    int lane = threadIdx.x & 31, wid = threadIdx.x >> 5;
    int v = (threadIdx.x < NB) ? g_bsum[threadIdx.x] : 0;
    int s = v;
    #pragma unroll
    for (int o = 1; o < 32; o <<= 1) {
        int t = __shfl_up_sync(0xffffffffu, s, o);
        if (lane >= o) s += t;
    }
    if (lane == 31) wsum[wid] = s;
    __syncthreads();
    if (wid == 0) {
        int w = (lane < 8) ? wsum[lane] : 0;
        #pragma unroll
        for (int o = 1; o < 8; o <<= 1) {
            int t = __shfl_up_sync(0xffffffffu, w, o);
            if (lane >= o) w += t;
        }
        if (lane < 8) wsum[lane] = w;
    }
    __syncthreads();
    int excl = s - v + (wid > 0 ? wsum[wid - 1] : 0);
    if (threadIdx.x < NB) g_bsum[threadIdx.x] = excl;
    if (threadIdx.x == NB - 1) g_offs[N_NODES] = excl + v;
}

__global__ __launch_bounds__(SCAN_B) void k_scanC() {
    int i = blockIdx.x * SCAN_B + threadIdx.x;
    if (i < N_NODES) g_offs[i] += g_bsum[blockIdx.x];
}

__global__ void k_fill(const int* __restrict__ pos_ei) {
    int e = blockIdx.x * blockDim.x + threadIdx.x;
    if (e < N_POS) {
        int s = pos_ei[e];
        int d = pos_ei[N_POS + e];
        int p = g_offs[d] + atomicAdd(&g_cur[d], 1);
        g_esrc[p] = s;
    }
}

// =================================================================
// WMMA GEMM body: 64-column tile of C[nrows][OUTC] = A[nrows][128] @ W
// bf16 hi/lo 3-pass split. 256 threads = 8 warps x 16 rows.
// SA=40 (80B stride) / SWS=72 (144B stride): conflict-free ldmatrix
// (banks 20i mod 32 resp. 36i mod 32 all distinct), 16B-aligned rows.
// =================================================================
#define SA 40            // A smem stride (elems) — conflict-free
#define CTILE 64         // columns per CTA
#define SWS 72           // W smem stride (elems) — conflict-free

template <int OUTC>
__device__ __forceinline__ void wmma_body(const float* __restrict__ A,
                                          const __nv_bfloat16* __restrict__ Wh,
                                          const __nv_bfloat16* __restrict__ Wl,
                                          float* __restrict__ C, int nrows) {
    __shared__ alignas(256) __nv_bfloat16 sAh[128 * SA];
    __shared__ alignas(256) __nv_bfloat16 sAl[128 * SA];
    __shared__ alignas(256) __nv_bfloat16 sWh[32 * SWS];
    __shared__ alignas(256) __nv_bfloat16 sWl[32 * SWS];

    const int tid  = threadIdx.x;
    const int warp = tid >> 5;
    const int row0 = blockIdx.x * 128;
    const int col0 = blockIdx.y * CTILE;

    constexpr int NT = CTILE / 16;   // 4
    wmma::fragment<wmma::accumulator, 16, 16, 16, float> acc[NT];
    #pragma unroll
    for (int nt = 0; nt < NT; nt++) wmma::fill_fragment(acc[nt], 0.0f);

    for (int kb = 0; kb < 128; kb += 32) {
        // ---- stage A chunk [128 x 32] as bf16 hi/lo (convert) ----
        for (int idx = tid * 4; idx < 128 * 32; idx += 1024) {
            int r = idx >> 5, c = idx & 31;
            int grow = row0 + r;
            float4 v = make_float4(0.f, 0.f, 0.f, 0.f);
            if (grow < nrows) v = *(const float4*)(A + (size_t)grow * 128 + kb + c);
            uint32_t h0 = pack2(v.x, v.y), h1 = pack2(v.z, v.w);
            uint32_t l0 = pack2(v.x - bf16_round(v.x), v.y - bf16_round(v.y));
            uint32_t l1 = pack2(v.z - bf16_round(v.z), v.w - bf16_round(v.w));
            *(uint2*)(sAh + r * SA + c) = make_uint2(h0, h1);
            *(uint2*)(sAl + r * SA + c) = make_uint2(l0, l1);
        }
        // ---- stage W chunk [32 x CTILE]: pure vector copy of bf16 planes ----
        for (int idx = tid * 8; idx < 32 * CTILE; idx += 2048) {
            int kr = idx / CTILE, n = idx % CTILE;
            *(uint4*)(sWh + kr * SWS + n) =
                *(const uint4*)(Wh + (size_t)(kb + kr) * OUTC + col0 + n);
            *(uint4*)(sWl + kr * SWS + n) =
                *(const uint4*)(Wl + (size_t)(kb + kr) * OUTC + col0 + n);
        }
        __syncthreads();

        #pragma unroll
        for (int kk = 0; kk < 32; kk += 16) {
            wmma::fragment<wmma::matrix_a, 16, 16, 16, __nv_bfloat16, wmma::row_major> fah, fal;
            wmma::load_matrix_sync(fah, sAh + warp * 16 * SA + kk, SA);
            wmma::load_matrix_sync(fal, sAl + warp * 16 * SA + kk, SA);
            #pragma unroll
            for (int nt = 0; nt < NT; nt++) {
                wmma::fragment<wmma::matrix_b, 16, 16, 16, __nv_bfloat16, wmma::row_major> fbh, fbl;
                wmma::load_matrix_sync(fbh, sWh + kk * SWS + nt * 16, SWS);
                wmma::load_matrix_sync(fbl, sWl + kk * SWS + nt * 16, SWS);
                wmma::mma_sync(acc[nt], fah, fbh, acc[nt]);
                wmma::mma_sync(acc[nt], fah, fbl, acc[nt]);
                wmma::mma_sync(acc[nt], fal, fbh, acc[nt]);
            }
        }
        __syncthreads();
    }

    int wr = row0 + warp * 16;
    if (wr + 16 <= nrows) {
        #pragma unroll
        for (int nt = 0; nt < NT; nt++)
            wmma::store_matrix_sync(C + (size_t)wr * OUTC + col0 + nt * 16, acc[nt],
                                    OUTC, wmma::mem_row_major);
    }
}

// wrapper kernels: device-side references to the __device__ globals
__global__ __launch_bounds__(256) void k_wmma1(const float* __restrict__ x) {
    wmma_body<128>(x, gW1h, gW1l, g_h1, N_NODES);
}
__global__ __launch_bounds__(256) void k_wmma2() {
    wmma_body<64>(g_z1, gW2h, gW2l, g_h2, N_NODES);
}

// ---------------- layer-1 aggregation: warp per dst node, 128 feats ----------------
__global__ void k_agg1(const float* __restrict__ b1) {
    int gw = (blockIdx.x * blockDim.x + threadIdx.x) >> 5;
    int lane = threadIdx.x & 31;
    if (gw >= N_NODES) return;
    int d = gw;
    float dv = g_dinv[d];
    float self = dv * dv;

    float4 h = ((const float4*)(g_h1 + (size_t)d * 128))[lane];
    float4 acc = make_float4(h.x * self, h.y * self, h.z * self, h.w * self);

    int e0 = g_offs[d], e1 = g_offs[d + 1];
    int j = e0;
    for (; j + 4 <= e1; j += 4) {
        int s0 = g_esrc[j], s1 = g_esrc[j + 1], s2 = g_esrc[j + 2], s3 = g_esrc[j + 3];
        float n0 = dv * g_dinv[s0];
        float n1 = dv * g_dinv[s1];
        float n2 = dv * g_dinv[s2];
        float n3 = dv * g_dinv[s3];
        float4 v0 = ((const float4*)(g_h1 + (size_t)s0 * 128))[lane];
        float4 v1 = ((const float4*)(g_h1 + (size_t)s1 * 128))[lane];
        float4 v2 = ((const float4*)(g_h1 + (size_t)s2 * 128))[lane];
        float4 v3 = ((const float4*)(g_h1 + (size_t)s3 * 128))[lane];
        acc.x += v0.x * n0 + v1.x * n1 + v2.x * n2 + v3.x * n3;
        acc.y += v0.y * n0 + v1.y * n1 + v2.y * n2 + v3.y * n3;
        acc.z += v0.z * n0 + v1.z * n1 + v2.z * n2 + v3.z * n3;
        acc.w += v0.w * n0 + v1.w * n1 + v2.w * n2 + v3.w * n3;
    }
    for (; j < e1; j++) {
        int s0 = g_esrc[j];
        float n0 = dv * g_dinv[s0];
        float4 v0 = ((const float4*)(g_h1 + (size_t)s0 * 128))[lane];
        acc.x += v0.x * n0; acc.y += v0.y * n0;
        acc.z += v0.z * n0; acc.w += v0.w * n0;
    }
    float4 bb = ((const float4*)b1)[lane];
    acc.x = fmaxf(acc.x + bb.x, 0.0f);
    acc.y = fmaxf(acc.y + bb.y, 0.0f);
    acc.z = fmaxf(acc.z + bb.z, 0.0f);
    acc.w = fmaxf(acc.w + bb.w, 0.0f);
    ((float4*)(g_z1 + (size_t)d * 128))[lane] = acc;
}

// ---------------- layer-2 aggregation: warp per dst node, 64 feats ----------------
__global__ void k_agg2(const float* __restrict__ b2) {
    int gw = (blockIdx.x * blockDim.x + threadIdx.x) >> 5;
    int lane = threadIdx.x & 31;
    if (gw >= N_NODES) return;
    int d = gw;
    float dv = g_dinv[d];
    float self = dv * dv;

    float2 h = ((const float2*)(g_h2 + (size_t)d * 64))[lane];
    float2 acc = make_float2(h.x * self, h.y * self);

    int e0 = g_offs[d], e1 = g_offs[d + 1];
    int j = e0;
    for (; j + 4 <= e1; j += 4) {
        int s0 = g_esrc[j], s1 = g_esrc[j + 1], s2 = g_esrc[j + 2], s3 = g_esrc[j + 3];
        float n0 = dv * g_dinv[s0];
        float n1 = dv * g_dinv[s1];
        float n2 = dv * g_dinv[s2];
        float n3 = dv * g_dinv[s3];
        float2 v0 = ((const float2*)(g_h2 + (size_t)s0 * 64))[lane];
        float2 v1 = ((const float2*)(g_h2 + (size_t)s1 * 64))[lane];
        float2 v2 = ((const float2*)(g_h2 + (size_t)s2 * 64))[lane];
        float2 v3 = ((const float2*)(g_h2 + (size_t)s3 * 64))[lane];
        acc.x += v0.x * n0 + v1.x * n1 + v2.x * n2 + v3.x * n3;
        acc.y += v0.y * n0 + v1.y * n1 + v2.y * n2 + v3.y * n3;
    }
    for (; j < e1; j++) {
        int s0 = g_esrc[j];
        float n0 = dv * g_dinv[s0];
        float2 v0 = ((const float2*)(g_h2 + (size_t)s0 * 64))[lane];
        acc.x += v0.x * n0; acc.y += v0.y * n0;
    }
    float2 bb = ((const float2*)b2)[lane];
    acc.x += bb.x; acc.y += bb.y;
    ((float2*)(g_z2 + (size_t)d * 64))[lane] = acc;
}

// ---------------- decode: warp per 2 edges, dot over 64 feats ----------------
__global__ void k_decode(const int* __restrict__ pos_ei,
                         const int* __restrict__ neg_ei,
                         float* __restrict__ out) {
    int w = (blockIdx.x * blockDim.x + threadIdx.x) >> 5;
    int lane = threadIdx.x & 31;
    int ea = w * 2;
    if (ea >= N_EDGES_TOT) return;
    int eb = ea + 1;
    bool has_b = (eb < N_EDGES_TOT);

    int a0, b0, a1 = 0, b1 = 0;
    if (ea < N_POS) { a0 = pos_ei[ea]; b0 = pos_ei[N_POS + ea]; }
    else { int f = ea - N_POS; a0 = neg_ei[f]; b0 = neg_ei[N_POS + f]; }
    if (has_b) {
        if (eb < N_POS) { a1 = pos_ei[eb]; b1 = pos_ei[N_POS + eb]; }
        else { int f = eb - N_POS; a1 = neg_ei[f]; b1 = neg_ei[N_POS + f]; }
    }

    float2 u0 = ((const float2*)(g_z2 + (size_t)a0 * 64))[lane];
    float2 v0 = ((const float2*)(g_z2 + (size_t)b0 * 64))[lane];
    float2 u1 = make_float2(0.f, 0.f), v1 = make_float2(0.f, 0.f);
    if (has_b) {
        u1 = ((const float2*)(g_z2 + (size_t)a1 * 64))[lane];
        v1 = ((const float2*)(g_z2 + (size_t)b1 * 64))[lane];
    }
    float s0 = u0.x * v0.x + u0.y * v0.y;
    float s1 = u1.x * v1.x + u1.y * v1.y;
    #pragma unroll
    for (int o = 16; o > 0; o >>= 1) {
        s0 += __shfl_xor_sync(0xffffffffu, s0, o);
        s1 += __shfl_xor_sync(0xffffffffu, s1, o);
    }
    if (lane == 0) {
        out[ea] = s0;
        if (has_b) out[eb] = s1;
    }
}

// ---------------- launch ----------------
extern "C" void kernel_launch(void* const* d_in, const int* in_sizes, int n_in,
                              void* d_out, int out_size) {
    const float* x   = (const float*)d_in[0];
    const int*   pos = (const int*)d_in[1];
    const int*   neg = (const int*)d_in[2];
    const float* W1  = (const float*)d_in[3];
    const float* b1  = (const float*)d_in[4];
    const float* W2  = (const float*)d_in[5];
    const float* b2  = (const float*)d_in[6];
    float* out = (float*)d_out;

    const int T = 256;
    const int GB = (N_NODES + 127) / 128;   // 782 row blocks

    // order chosen so launch #4 (ncu capture slot) is k_wmma1
    k_zero<<<(N_NODES + T - 1) / T, T>>>();                       // 1
    k_hist<<<(N_POS + T - 1) / T, T>>>(pos);                      // 2
    k_cvtW<<<(128 * 128 + T - 1) / T, T>>>(W1, W2);               // 3
    k_wmma1<<<dim3(GB, 2), 256>>>(x);                             // 4  <- profiled
    k_scanA<<<NB, SCAN_B>>>();                                    // 5
    k_scanB<<<1, 256>>>();                                        // 6
    k_scanC<<<NB, SCAN_B>>>();                                    // 7
    k_fill<<<(N_POS + T - 1) / T, T>>>(pos);                      // 8
    k_agg1<<<(N_NODES * 32 + T - 1) / T, T>>>(b1);                // 9
    k_wmma2<<<dim3(GB, 1), 256>>>();                              // 10
    k_agg2<<<(N_NODES * 32 + T - 1) / T, T>>>(b2);                // 11
    k_decode<<<((size_t)(N_EDGES_TOT / 2 + 1) * 32 + T - 1) / T, T>>>(pos, neg, out); // 12
}

// round 11
// speedup vs baseline: 1.8182x; 1.0021x over previous
#include <cuda_runtime.h>
#include <cuda_bf16.h>
#include <mma.h>
#include <math.h>
#include <stdint.h>

using namespace nvcuda;

#define N_NODES 100000
#define IN_CH   128
#define HIDDEN  128
#define OUT_CH  64
#define N_POS   600000
#define N_EDGES_TOT 1200000

#define SCAN_B 512
#define NB ((N_NODES + SCAN_B - 1) / SCAN_B)   // 196

// ---------------- scratch (no cudaMalloc allowed) ----------------
__device__ float g_h1[(size_t)N_NODES * HIDDEN];   // x @ W1
__device__ float g_h2[(size_t)N_NODES * OUT_CH];   // z1 @ W2
__device__ float g_z2[(size_t)N_NODES * OUT_CH];   // agg2 + b2
__device__ float g_dinv[N_NODES];
__device__ int   g_cnt[N_NODES];
__device__ int   g_cur[N_NODES];
__device__ int   g_offs[N_NODES + 1];
__device__ int   g_esrc[N_POS];
__device__ int   g_bsum[NB];
// bf16 hi/lo planes
__device__ __nv_bfloat16 gXh[(size_t)N_NODES * 128], gXl[(size_t)N_NODES * 128];
__device__ __nv_bfloat16 gZ1h[(size_t)N_NODES * 128], gZ1l[(size_t)N_NODES * 128];
__device__ __nv_bfloat16 gW1h[128 * 128], gW1l[128 * 128];
__device__ __nv_bfloat16 gW2h[128 * 64],  gW2l[128 * 64];

// ---------------- helpers ----------------
__device__ __forceinline__ uint32_t pack2(float a, float b) {
    uint32_t r;
    asm("cvt.rn.satfinite.bf16x2.f32 %0, %1, %2;" : "=r"(r) : "f"(b), "f"(a));
    return r;
}
__device__ __forceinline__ float bf16_round(float v) {
    return __bfloat162float(__float2bfloat16(v));
}
__device__ __forceinline__ void cvt4(float4 v, uint2& h, uint2& l) {
    h = make_uint2(pack2(v.x, v.y), pack2(v.z, v.w));
    l = make_uint2(pack2(v.x - bf16_round(v.x), v.y - bf16_round(v.y)),
                   pack2(v.z - bf16_round(v.z), v.w - bf16_round(v.w)));
}

// ---------------- CSR build ----------------
__global__ void k_zero() {
    int i = blockIdx.x * blockDim.x + threadIdx.x;
    if (i < N_NODES) { g_cnt[i] = 0; g_cur[i] = 0; }
}

__global__ void k_hist(const int* __restrict__ pos_ei) {
    int e = blockIdx.x * blockDim.x + threadIdx.x;
    if (e < N_POS) {
        int d = pos_ei[N_POS + e];
        atomicAdd(&g_cnt[d], 1);
    }
}

// convert x, W1, W2 to bf16 hi/lo planes
__global__ void k_cvt(const float* __restrict__ x,
                      const float* __restrict__ W1,
                      const float* __restrict__ W2) {
    int i = blockIdx.x * blockDim.x + threadIdx.x;   // float4 group index
    if (i < (N_NODES * 128) / 4) {
        float4 v = ((const float4*)x)[i];
        uint2 h, l; cvt4(v, h, l);
        ((uint2*)gXh)[i] = h;
        ((uint2*)gXl)[i] = l;
    }
    if (i < (128 * 128) / 4) {
        float4 v = ((const float4*)W1)[i];
        uint2 h, l; cvt4(v, h, l);
        ((uint2*)gW1h)[i] = h;
        ((uint2*)gW1l)[i] = l;
    }
    if (i < (128 * 64) / 4) {
        float4 v = ((const float4*)W2)[i];
        uint2 h, l; cvt4(v, h, l);
        ((uint2*)gW2h)[i] = h;
        ((uint2*)gW2l)[i] = l;
    }
}

__global__ __launch_bounds__(SCAN_B) void k_scanA() {
    __shared__ int wsum[16];
    int i = blockIdx.x * SCAN_B + threadIdx.x;
    int lane = threadIdx.x & 31, wid = threadIdx.x >> 5;
    int v = (i < N_NODES) ? g_cnt[i] : 0;
    if (i < N_NODES) g_dinv[i] = rsqrtf((float)v + 1.0f);

    int s = v;
    #pragma unroll
    for (int o = 1; o < 32; o <<= 1) {
        int t = __shfl_up_sync(0xffffffffu, s, o);
        if (lane >= o) s += t;
    }
    if (lane == 31) wsum[wid] = s;
    __syncthreads();
    if (wid == 0) {
        int w = (lane < 16) ? wsum[lane] : 0;
        #pragma unroll
        for (int o = 1; o < 16; o <<= 1) {
            int t = __shfl_up_sync(0xffffffffu, w, o);
            if (lane >= o) w += t;
        }
        if (lane < 16) wsum[lane] = w;
    }
    __syncthreads();
    int excl = s - v + (wid > 0 ? wsum[wid - 1] : 0);
    if (i < N_NODES) g_offs[i] = excl;
    if (threadIdx.x == 0) g_bsum[blockIdx.x] = wsum[15];
}

__global__ __launch_bounds__(256) void k_scanB() {
    __shared__ int wsum[8];
    int lane = threadIdx.x & 31, wid = threadIdx.x >> 5;
    int v = (threadIdx.x < NB) ? g_bsum[threadIdx.x] : 0;
    int s = v;
    #pragma unroll
    for (int o = 1; o < 32; o <<= 1) {
        int t = __shfl_up_sync(0xffffffffu, s, o);
        if (lane >= o) s += t;
    }
    if (lane == 31) wsum[wid] = s;
    __syncthreads();
    if (wid == 0) {
        int w = (lane < 8) ? wsum[lane] : 0;
        #pragma unroll
        for (int o = 1; o < 8; o <<= 1) {
            int t = __shfl_up_sync(0xffffffffu, w, o);
            if (lane >= o) w += t;
        }
        if (lane < 8) wsum[lane] = w;
    }
    __syncthreads();
    int excl = s - v + (wid > 0 ? wsum[wid - 1] : 0);
    if (threadIdx.x < NB) g_bsum[threadIdx.x] = excl;
    if (threadIdx.x == NB - 1) g_offs[N_NODES] = excl + v;
}

__global__ __launch_bounds__(SCAN_B) void k_scanC() {
    int i = blockIdx.x * SCAN_B + threadIdx.x;
    if (i < N_NODES) g_offs[i] += g_bsum[blockIdx.x];
}

__global__ void k_fill(const int* __restrict__ pos_ei) {
    int e = blockIdx.x * blockDim.x + threadIdx.x;
    if (e < N_POS) {
        int s = pos_ei[e];
        int d = pos_ei[N_POS + e];
        int p = g_offs[d] + atomicAdd(&g_cur[d], 1);
        g_esrc[p] = s;
    }
}

// =================================================================
// WMMA GEMM body: 64-column tile of C[nrows][OUTC] = A[nrows][128] @ W
// A given as pre-converted bf16 hi/lo planes -> staging is pure copies.
// bf16 hi/lo 3-pass split. 256 threads = 8 warps x 16 rows.
// SA=40 / SWS=72: conflict-free ldmatrix, 16B-aligned rows.
// =================================================================
#define SA 40            // A smem stride (elems) — conflict-free
#define CTILE 64         // columns per CTA
#define SWS 72           // W smem stride (elems) — conflict-free

template <int OUTC>
__device__ __forceinline__ void wmma_body(const __nv_bfloat16* __restrict__ Ah,
                                          const __nv_bfloat16* __restrict__ Al,
                                          const __nv_bfloat16* __restrict__ Wh,
                                          const __nv_bfloat16* __restrict__ Wl,
                                          float* __restrict__ C, int nrows) {
    __shared__ alignas(256) __nv_bfloat16 sAh[128 * SA];
    __shared__ alignas(256) __nv_bfloat16 sAl[128 * SA];
    __shared__ alignas(256) __nv_bfloat16 sWh[32 * SWS];
    __shared__ alignas(256) __nv_bfloat16 sWl[32 * SWS];

    const int tid  = threadIdx.x;
    const int warp = tid >> 5;
    const int row0 = blockIdx.x * 128;
    const int col0 = blockIdx.y * CTILE;

    constexpr int NT = CTILE / 16;   // 4
    wmma::fragment<wmma::accumulator, 16, 16, 16, float> acc[NT];
    #pragma unroll
    for (int nt = 0; nt < NT; nt++) wmma::fill_fragment(acc[nt], 0.0f);

    const uint4 uz = make_uint4(0u, 0u, 0u, 0u);

    for (int kb = 0; kb < 128; kb += 32) {
        // ---- stage A chunk [128 x 32]: pure vector copy of bf16 planes ----
        for (int idx = tid * 8; idx < 128 * 32; idx += 2048) {
            int r = idx >> 5, c = idx & 31;
            int grow = row0 + r;
            size_t goff = (size_t)grow * 128 + kb + c;
            uint4 vh = uz, vl = uz;
            if (grow < nrows) {
                vh = *(const uint4*)(Ah + goff);
                vl = *(const uint4*)(Al + goff);
            }
            *(uint4*)(sAh + r * SA + c) = vh;
            *(uint4*)(sAl + r * SA + c) = vl;
        }
        // ---- stage W chunk [32 x CTILE]: pure vector copy of bf16 planes ----
        for (int idx = tid * 8; idx < 32 * CTILE; idx += 2048) {
            int kr = idx / CTILE, n = idx % CTILE;
            *(uint4*)(sWh + kr * SWS + n) =
                *(const uint4*)(Wh + (size_t)(kb + kr) * OUTC + col0 + n);
            *(uint4*)(sWl + kr * SWS + n) =
                *(const uint4*)(Wl + (size_t)(kb + kr) * OUTC + col0 + n);
        }
        __syncthreads();

        #pragma unroll
        for (int kk = 0; kk < 32; kk += 16) {
            wmma::fragment<wmma::matrix_a, 16, 16, 16, __nv_bfloat16, wmma::row_major> fah, fal;
            wmma::load_matrix_sync(fah, sAh + warp * 16 * SA + kk, SA);
            wmma::load_matrix_sync(fal, sAl + warp * 16 * SA + kk, SA);
            #pragma unroll
            for (int nt = 0; nt < NT; nt++) {
                wmma::fragment<wmma::matrix_b, 16, 16, 16, __nv_bfloat16, wmma::row_major> fbh, fbl;
                wmma::load_matrix_sync(fbh, sWh + kk * SWS + nt * 16, SWS);
                wmma::load_matrix_sync(fbl, sWl + kk * SWS + nt * 16, SWS);
                wmma::mma_sync(acc[nt], fah, fbh, acc[nt]);
                wmma::mma_sync(acc[nt], fah, fbl, acc[nt]);
                wmma::mma_sync(acc[nt], fal, fbh, acc[nt]);
            }
        }
        __syncthreads();
    }

    int wr = row0 + warp * 16;
    if (wr + 16 <= nrows) {
        #pragma unroll
        for (int nt = 0; nt < NT; nt++)
            wmma::store_matrix_sync(C + (size_t)wr * OUTC + col0 + nt * 16, acc[nt],
                                    OUTC, wmma::mem_row_major);
    }
}

// wrapper kernels: device-side references to the __device__ globals
__global__ __launch_bounds__(256) void k_wmma1() {
    wmma_body<128>(gXh, gXl, gW1h, gW1l, g_h1, N_NODES);
}
__global__ __launch_bounds__(256) void k_wmma2() {
    wmma_body<64>(gZ1h, gZ1l, gW2h, gW2l, g_h2, N_NODES);
}

// ---------------- layer-1 aggregation: warp per dst node, 128 feats ----------------
// epilogue writes z1 directly as bf16 hi/lo planes (consumed by k_wmma2)
__global__ void k_agg1(const float* __restrict__ b1) {
    int gw = (blockIdx.x * blockDim.x + threadIdx.x) >> 5;
    int lane = threadIdx.x & 31;
    if (gw >= N_NODES) return;
    int d = gw;
    float dv = g_dinv[d];
    float self = dv * dv;

    float4 h = ((const float4*)(g_h1 + (size_t)d * 128))[lane];
    float4 acc = make_float4(h.x * self, h.y * self, h.z * self, h.w * self);

    int e0 = g_offs[d], e1 = g_offs[d + 1];
    int j = e0;
    for (; j + 4 <= e1; j += 4) {
        int s0 = g_esrc[j], s1 = g_esrc[j + 1], s2 = g_esrc[j + 2], s3 = g_esrc[j + 3];
        float n0 = dv * g_dinv[s0];
        float n1 = dv * g_dinv[s1];
        float n2 = dv * g_dinv[s2];
        float n3 = dv * g_dinv[s3];
        float4 v0 = ((const float4*)(g_h1 + (size_t)s0 * 128))[lane];
        float4 v1 = ((const float4*)(g_h1 + (size_t)s1 * 128))[lane];
        float4 v2 = ((const float4*)(g_h1 + (size_t)s2 * 128))[lane];
        float4 v3 = ((const float4*)(g_h1 + (size_t)s3 * 128))[lane];
        acc.x += v0.x * n0 + v1.x * n1 + v2.x * n2 + v3.x * n3;
        acc.y += v0.y * n0 + v1.y * n1 + v2.y * n2 + v3.y * n3;
        acc.z += v0.z * n0 + v1.z * n1 + v2.z * n2 + v3.z * n3;
        acc.w += v0.w * n0 + v1.w * n1 + v2.w * n2 + v3.w * n3;
    }
    for (; j < e1; j++) {
        int s0 = g_esrc[j];
        float n0 = dv * g_dinv[s0];
        float4 v0 = ((const float4*)(g_h1 + (size_t)s0 * 128))[lane];
        acc.x += v0.x * n0; acc.y += v0.y * n0;
        acc.z += v0.z * n0; acc.w += v0.w * n0;
    }
    float4 bb = ((const float4*)b1)[lane];
    acc.x = fmaxf(acc.x + bb.x, 0.0f);
    acc.y = fmaxf(acc.y + bb.y, 0.0f);
    acc.z = fmaxf(acc.z + bb.z, 0.0f);
    acc.w = fmaxf(acc.w + bb.w, 0.0f);
    uint2 hh, ll; cvt4(acc, hh, ll);
    ((uint2*)(gZ1h + (size_t)d * 128))[lane] = hh;
    ((uint2*)(gZ1l + (size_t)d * 128))[lane] = ll;
}

// ---------------- layer-2 aggregation: warp per dst node, 64 feats ----------------
__global__ void k_agg2(const float* __restrict__ b2) {
    int gw = (blockIdx.x * blockDim.x + threadIdx.x) >> 5;
    int lane = threadIdx.x & 31;
    if (gw >= N_NODES) return;
    int d = gw;
    float dv = g_dinv[d];
    float self = dv * dv;

    float2 h = ((const float2*)(g_h2 + (size_t)d * 64))[lane];
    float2 acc = make_float2(h.x * self, h.y * self);

    int e0 = g_offs[d], e1 = g_offs[d + 1];
    int j = e0;
    for (; j + 4 <= e1; j += 4) {
        int s0 = g_esrc[j], s1 = g_esrc[j + 1], s2 = g_esrc[j + 2], s3 = g_esrc[j + 3];
        float n0 = dv * g_dinv[s0];
        float n1 = dv * g_dinv[s1];
        float n2 = dv * g_dinv[s2];
        float n3 = dv * g_dinv[s3];
        float2 v0 = ((const float2*)(g_h2 + (size_t)s0 * 64))[lane];
        float2 v1 = ((const float2*)(g_h2 + (size_t)s1 * 64))[lane];
        float2 v2 = ((const float2*)(g_h2 + (size_t)s2 * 64))[lane];
        float2 v3 = ((const float2*)(g_h2 + (size_t)s3 * 64))[lane];
        acc.x += v0.x * n0 + v1.x * n1 + v2.x * n2 + v3.x * n3;
        acc.y += v0.y * n0 + v1.y * n1 + v2.y * n2 + v3.y * n3;
    }
    for (; j < e1; j++) {
        int s0 = g_esrc[j];
        float n0 = dv * g_dinv[s0];
        float2 v0 = ((const float2*)(g_h2 + (size_t)s0 * 64))[lane];
        acc.x += v0.x * n0; acc.y += v0.y * n0;
    }
    float2 bb = ((const float2*)b2)[lane];
    acc.x += bb.x; acc.y += bb.y;
    ((float2*)(g_z2 + (size_t)d * 64))[lane] = acc;
}

// ---------------- decode: warp per 2 edges, dot over 64 feats ----------------
__global__ void k_decode(const int* __restrict__ pos_ei,
                         const int* __restrict__ neg_ei,
                         float* __restrict__ out) {
    int w = (blockIdx.x * blockDim.x + threadIdx.x) >> 5;
    int lane = threadIdx.x & 31;
    int ea = w * 2;
    if (ea >= N_EDGES_TOT) return;
    int eb = ea + 1;
    bool has_b = (eb < N_EDGES_TOT);

    int a0, b0, a1 = 0, b1 = 0;
    if (ea < N_POS) { a0 = pos_ei[ea]; b0 = pos_ei[N_POS + ea]; }
    else { int f = ea - N_POS; a0 = neg_ei[f]; b0 = neg_ei[N_POS + f]; }
    if (has_b) {
        if (eb < N_POS) { a1 = pos_ei[eb]; b1 = pos_ei[N_POS + eb]; }
        else { int f = eb - N_POS; a1 = neg_ei[f]; b1 = neg_ei[N_POS + f]; }
    }

    float2 u0 = ((const float2*)(g_z2 + (size_t)a0 * 64))[lane];
    float2 v0 = ((const float2*)(g_z2 + (size_t)b0 * 64))[lane];
    float2 u1 = make_float2(0.f, 0.f), v1 = make_float2(0.f, 0.f);
    if (has_b) {
        u1 = ((const float2*)(g_z2 + (size_t)a1 * 64))[lane];
        v1 = ((const float2*)(g_z2 + (size_t)b1 * 64))[lane];
    }
    float s0 = u0.x * v0.x + u0.y * v0.y;
    float s1 = u1.x * v1.x + u1.y * v1.y;
    #pragma unroll
    for (int o = 16; o > 0; o >>= 1) {
        s0 += __shfl_xor_sync(0xffffffffu, s0, o);
        s1 += __shfl_xor_sync(0xffffffffu, s1, o);
    }
    if (lane == 0) {
        out[ea] = s0;
        if (has_b) out[eb] = s1;
    }
}

// ---------------- launch ----------------
extern "C" void kernel_launch(void* const* d_in, const int* in_sizes, int n_in,
                              void* d_out, int out_size) {
    const float* x   = (const float*)d_in[0];
    const int*   pos = (const int*)d_in[1];
    const int*   neg = (const int*)d_in[2];
    const float* W1  = (const float*)d_in[3];
    const float* b1  = (const float*)d_in[4];
    const float* W2  = (const float*)d_in[5];
    const float* b2  = (const float*)d_in[6];
    float* out = (float*)d_out;

    const int T = 256;
    const int GB = (N_NODES + 127) / 128;   // 782 row blocks

    // order chosen so launch #4 (ncu capture slot) is k_wmma1
    k_zero<<<(N_NODES + T - 1) / T, T>>>();                           // 1
    k_hist<<<(N_POS + T - 1) / T, T>>>(pos);                          // 2
    k_cvt<<<((N_NODES * 128) / 4 + T - 1) / T, T>>>(x, W1, W2);       // 3
    k_wmma1<<<dim3(GB, 2), 256>>>();                                  // 4  <- profiled
    k_scanA<<<NB, SCAN_B>>>();                                        // 5
    k_scanB<<<1, 256>>>();                                            // 6
    k_scanC<<<NB, SCAN_B>>>();                                        // 7
    k_fill<<<(N_POS + T - 1) / T, T>>>(pos);                          // 8
    k_agg1<<<(N_NODES * 32 + T - 1) / T, T>>>(b1);                    // 9
    k_wmma2<<<dim3(GB, 1), 256>>>();                                  // 10
    k_agg2<<<(N_NODES * 32 + T - 1) / T, T>>>(b2);                    // 11
    k_decode<<<((size_t)(N_EDGES_TOT / 2 + 1) * 32 + T - 1) / T, T>>>(pos, neg, out); // 12
}